// round 6
// baseline (speedup 1.0000x reference)
#include <cuda_runtime.h>
#include <cstdint>
#include <math.h>

// ---------------- problem constants ----------------
#define NB   4
#define SEQ  8192
#define DIM  1024
#define MTOT (NB*SEQ)          // 32768 rows

// ---------------- GEMM tiling ----------------------
#define BM 128
#define BN 128
#define BK 32                  // 32 fp32 per row-chunk = 128B data per row
#define ROW_STR 144            // padded row stride in bytes (conflict-free LDSM)
#define A_REGION (BM*ROW_STR)  // 18432 B
#define B_REGION (BN*ROW_STR)  // 18432 B
#define STAGE_BYTES (A_REGION + B_REGION)   // 36864 B
#define STAGES 3
#define GEMM_SMEM (STAGES*STAGE_BYTES)      // 110592 B -> 2 CTAs/SM
#define NK (DIM/BK)            // 32 k-tiles

// ---------------- device scratch --------------------
__device__ float g_X [(size_t)MTOT*DIM];   // x, tf32-rounded
__device__ float g_Q [(size_t)MTOT*DIM];   // Q (elu+1); later U (tf32-rounded)
__device__ float g_K [(size_t)MTOT*DIM];
__device__ float g_V [(size_t)MTOT*DIM];
__device__ float g_WT [(size_t)3*DIM*DIM]; // [n,k] transposed wq|wk|wv, tf32-rounded
__device__ float g_WoT[(size_t)DIM*DIM];   // [n,k] transposed wo, tf32-rounded
__device__ float g_bqkv[3*DIM];
__device__ float g_pKV[32][NB*DIM];
__device__ float g_pKs[32][NB*DIM];
__device__ float g_KV[NB*DIM];
__device__ float g_Ks[NB*DIM];

// ---------------- PTX helpers ----------------------
__device__ __forceinline__ uint32_t smem_u32(const void* p) {
    return (uint32_t)__cvta_generic_to_shared(p);
}
__device__ __forceinline__ void cp_async16(uint32_t smem_dst, const float* gsrc) {
    asm volatile("cp.async.cg.shared.global [%0], [%1], 16;\n" :: "r"(smem_dst), "l"(gsrc));
}
#define CP_COMMIT() asm volatile("cp.async.commit_group;\n")
#define CP_WAIT(n)  asm volatile("cp.async.wait_group %0;\n" :: "n"(n))

__device__ __forceinline__ uint32_t f2tf(float f) {   // round-to-nearest tf32 in fp32 container
    uint32_t u;
    asm("cvt.rna.tf32.f32 %0, %1;" : "=r"(u) : "f"(f));
    return u;
}
__device__ __forceinline__ float rna_tf32(float f) { return __uint_as_float(f2tf(f)); }

__device__ __forceinline__ void ldsm_x4(uint32_t& r0, uint32_t& r1, uint32_t& r2, uint32_t& r3,
                                        uint32_t saddr) {
    asm volatile("ldmatrix.sync.aligned.m8n8.x4.shared.b16 {%0,%1,%2,%3}, [%4];"
                 : "=r"(r0), "=r"(r1), "=r"(r2), "=r"(r3) : "r"(saddr));
}

__device__ __forceinline__ void mma_tf32(float& d0, float& d1, float& d2, float& d3,
                                         uint32_t a0, uint32_t a1, uint32_t a2, uint32_t a3,
                                         uint32_t b0, uint32_t b1) {
    asm volatile(
        "mma.sync.aligned.m16n8k8.row.col.f32.tf32.tf32.f32 "
        "{%0,%1,%2,%3},{%4,%5,%6,%7},{%8,%9},{%0,%1,%2,%3};\n"
        : "+f"(d0), "+f"(d1), "+f"(d2), "+f"(d3)
        : "r"(a0), "r"(a1), "r"(a2), "r"(a3), "r"(b0), "r"(b1));
}

// ---------------- stage loader (cp.async, padded rows) ----------------------
// A: [m0..m0+127][kb..kb+31] row-major lda=DIM; BT: [n0..n0+127][kb..kb+31]
__device__ __forceinline__ void load_stage(const float* __restrict__ A,
                                           const float* __restrict__ BT,
                                           int m0, int n0, int kt,
                                           uint32_t smem_base, int stage) {
    const int tid = threadIdx.x;
    const uint32_t base = smem_base + stage * STAGE_BYTES;
    const int kb = kt * BK;
#pragma unroll
    for (int i = 0; i < 4; i++) {
        const int idx = tid + 256 * i;          // 1024 chunks of 16B
        const int r = idx >> 3, c = idx & 7;
        cp_async16(base + r * ROW_STR + c * 16,
                   A + (size_t)(m0 + r) * DIM + kb + c * 4);
    }
    const uint32_t bbase = base + A_REGION;
#pragma unroll
    for (int i = 0; i < 4; i++) {
        const int idx = tid + 256 * i;
        const int r = idx >> 3, c = idx & 7;
        cp_async16(bbase + r * ROW_STR + c * 16,
                   BT + (size_t)(n0 + r) * DIM + kb + c * 4);
    }
    CP_COMMIT();
}

// ---------------- GEMM: D[128,128] = A[128,1024] @ BT[128,1024]^T -----------
// MODE 0: A=g_X, BT=g_WT (3072 rows), bias=g_bqkv -> g_Q/g_K/g_V (elu+1 on q,k)
// MODE 1: A=g_Q (U), BT=g_WoT, bias=bo -> out (gelu)
template <int MODE>
__global__ void __launch_bounds__(256, 2)
gemm_tc(const float* __restrict__ bias_ext, float* __restrict__ out0) {
    extern __shared__ char smem[];
    const uint32_t sb = smem_u32(smem);
    const int tid = threadIdx.x;
    const int wid = tid >> 5, lane = tid & 31;
    const int n0 = blockIdx.x * BN;
    const int m0 = blockIdx.y * BM;

    const float* A    = (MODE == 0) ? g_X  : g_Q;
    const float* BT   = (MODE == 0) ? g_WT : g_WoT;
    const float* bias = (MODE == 0) ? g_bqkv : bias_ext;

    // prologue: 2 stages in flight
    load_stage(A, BT, m0, n0, 0, sb, 0);
    load_stage(A, BT, m0, n0, 1, sb, 1);

    // warp layout: 2 (M) x 4 (N); warp tile 64x32
    const int wm = wid & 1, wn = wid >> 1;
    const int r16 = lane & 15, half = lane >> 4;

    // LDSM base offsets within a stage (A: 4 m-subtiles; B: 2 n-pair subtiles)
    uint32_t aoff[4], boff[2];
#pragma unroll
    for (int mt = 0; mt < 4; mt++)
        aoff[mt] = (uint32_t)(wm * 64 + mt * 16 + r16) * ROW_STR + half * 16;
#pragma unroll
    for (int p = 0; p < 2; p++)
        boff[p] = A_REGION + (uint32_t)(wn * 32 + p * 16 + r16) * ROW_STR + half * 16;

    float acc[4][4][4] = {};

    for (int kt = 0; kt < NK; kt++) {
        const int stage = kt % STAGES;
        CP_WAIT(1);
        __syncthreads();
        if (kt + 2 < NK) load_stage(A, BT, m0, n0, kt + 2, sb, (kt + 2) % STAGES);
        else             CP_COMMIT();   // keep group count uniform

        const uint32_t base = sb + stage * STAGE_BYTES;
#pragma unroll
        for (int ks = 0; ks < 4; ks++) {         // 4 x (k=8) per 32-float chunk
            uint32_t af[4][4], bf[2][4];
#pragma unroll
            for (int mt = 0; mt < 4; mt++)
                ldsm_x4(af[mt][0], af[mt][1], af[mt][2], af[mt][3],
                        base + aoff[mt] + ks * 32);
#pragma unroll
            for (int p = 0; p < 2; p++)
                ldsm_x4(bf[p][0], bf[p][1], bf[p][2], bf[p][3],
                        base + boff[p] + ks * 32);
#pragma unroll
            for (int mt = 0; mt < 4; mt++)
#pragma unroll
                for (int nt = 0; nt < 4; nt++)
                    mma_tf32(acc[mt][nt][0], acc[mt][nt][1], acc[mt][nt][2], acc[mt][nt][3],
                             af[mt][0], af[mt][1], af[mt][2], af[mt][3],
                             bf[nt >> 1][nt & 1], bf[nt >> 1][2 + (nt & 1)]);
        }
    }

    // ---- epilogue ----
    const int g = lane >> 2, t = lane & 3;
    float* dst;
    const float* bptr = bias + ((MODE == 0) ? n0 : n0);
    bool act_elu = false;
    if (MODE == 0) {
        const int which = n0 >> 10;               // 0:q 1:k 2:v
        float* outp = (which == 0) ? g_Q : (which == 1) ? g_K : g_V;
        dst = outp + (n0 & 1023);
        act_elu = (which < 2);
    } else {
        dst = out0 + n0;
    }

#pragma unroll
    for (int mt = 0; mt < 4; mt++) {
#pragma unroll
        for (int nt = 0; nt < 4; nt++) {
            const int col  = wn * 32 + nt * 8 + t * 2;
            const int row0 = m0 + wm * 64 + mt * 16 + g;
            const float b0v = bptr[col], b1v = bptr[col + 1];
            float v0 = acc[mt][nt][0] + b0v;
            float v1 = acc[mt][nt][1] + b1v;
            float v2 = acc[mt][nt][2] + b0v;
            float v3 = acc[mt][nt][3] + b1v;
            if (MODE == 0) {
                if (act_elu) {   // elu(x)+1
                    v0 = (v0 > 0.f) ? v0 + 1.f : __expf(v0);
                    v1 = (v1 > 0.f) ? v1 + 1.f : __expf(v1);
                    v2 = (v2 > 0.f) ? v2 + 1.f : __expf(v2);
                    v3 = (v3 > 0.f) ? v3 + 1.f : __expf(v3);
                }
            } else {             // gelu_tanh(v) = v * sigmoid(2u)
                const float c0 = 0.7978845608028654f, c1 = 0.044715f;
                float u;
                u = c0 * (v0 + c1 * v0 * v0 * v0); v0 = v0 / (1.f + __expf(-2.f * u));
                u = c0 * (v1 + c1 * v1 * v1 * v1); v1 = v1 / (1.f + __expf(-2.f * u));
                u = c0 * (v2 + c1 * v2 * v2 * v2); v2 = v2 / (1.f + __expf(-2.f * u));
                u = c0 * (v3 + c1 * v3 * v3 * v3); v3 = v3 / (1.f + __expf(-2.f * u));
            }
            *(float2*)(dst + (size_t)row0 * DIM + col)       = make_float2(v0, v1);
            *(float2*)(dst + (size_t)(row0 + 8) * DIM + col) = make_float2(v2, v3);
        }
    }
}

// ---------------- prep kernels ----------------------------------------------
__global__ void round_x(const float* __restrict__ x) {
    const size_t i = (size_t)blockIdx.x * 256 + threadIdx.x;   // 8M float4
    float4 v = ((const float4*)x)[i];
    v.x = rna_tf32(v.x); v.y = rna_tf32(v.y); v.z = rna_tf32(v.z); v.w = rna_tf32(v.w);
    ((float4*)g_X)[i] = v;
}

__global__ void transpose_w(const float* __restrict__ wq, const float* __restrict__ wk,
                            const float* __restrict__ wv, const float* __restrict__ wo) {
    __shared__ float t[32][33];
    const int mz = blockIdx.z;
    const float* W = (mz == 0) ? wq : (mz == 1) ? wk : (mz == 2) ? wv : wo;
    float* DT = (mz < 3) ? (g_WT + (size_t)mz * DIM * DIM) : g_WoT;
    const int k0 = blockIdx.y * 32, nn0 = blockIdx.x * 32;
#pragma unroll
    for (int i = 0; i < 32; i += 8)
        t[threadIdx.y + i][threadIdx.x] = W[(size_t)(k0 + threadIdx.y + i) * DIM + nn0 + threadIdx.x];
    __syncthreads();
#pragma unroll
    for (int i = 0; i < 32; i += 8)
        DT[(size_t)(nn0 + threadIdx.y + i) * DIM + k0 + threadIdx.x] =
            rna_tf32(t[threadIdx.x][threadIdx.y + i]);
}

__global__ void pack_bias(const float* __restrict__ bq, const float* __restrict__ bk,
                          const float* __restrict__ bv) {
    const int i = blockIdx.x * 256 + threadIdx.x;   // 0..3071
    g_bqkv[i] = (i < 1024) ? bq[i] : (i < 2048) ? bk[i - 1024] : bv[i - 2048];
}

// ---------------- reductions + normalization --------------------------------
__global__ void reduce_partial() {
    const int h  = blockIdx.x * 128 + threadIdx.x;
    const int sc = blockIdx.y;
    const int n  = blockIdx.z;
    const size_t base = ((size_t)(n * SEQ + sc * 256)) * DIM + h;
    const float* Kp = g_K + base;
    const float* Vp = g_V + base;
    float kv = 0.f, ks = 0.f;
#pragma unroll 8
    for (int i = 0; i < 256; i++) {
        const float k = Kp[(size_t)i * DIM];
        const float v = Vp[(size_t)i * DIM];
        kv = fmaf(k, v, kv);
        ks += k;
    }
    g_pKV[sc][n * DIM + h] = kv;
    g_pKs[sc][n * DIM + h] = ks;
}

__global__ void reduce_final() {
    const int idx = blockIdx.x * blockDim.x + threadIdx.x;
    float kv = 0.f, ks = 0.f;
#pragma unroll
    for (int i = 0; i < 32; i++) { kv += g_pKV[i][idx]; ks += g_pKs[i][idx]; }
    g_KV[idx] = kv;
    g_Ks[idx] = ks;
}

__global__ void apply_u() {   // U = Q*KV / (Q*Ksum + 1e-6), rna-rounded, in place
    const size_t i4 = (size_t)blockIdx.x * 256 + threadIdx.x;
    const size_t f  = i4 * 4;
    const int n = (int)(f >> 23);
    const int h = (int)(f & 1023);
    float4 q = ((float4*)g_Q)[i4];
    const float4 kv = *(const float4*)(g_KV + n * DIM + h);
    const float4 ks = *(const float4*)(g_Ks + n * DIM + h);
    q.x = rna_tf32(q.x * kv.x / fmaf(q.x, ks.x, 1e-6f));
    q.y = rna_tf32(q.y * kv.y / fmaf(q.y, ks.y, 1e-6f));
    q.z = rna_tf32(q.z * kv.z / fmaf(q.z, ks.z, 1e-6f));
    q.w = rna_tf32(q.w * kv.w / fmaf(q.w, ks.w, 1e-6f));
    ((float4*)g_Q)[i4] = q;
}

// ---------------- launch -----------------------------------------------------
extern "C" void kernel_launch(void* const* d_in, const int* in_sizes, int n_in,
                              void* d_out, int out_size) {
    const float* x  = (const float*)d_in[0];
    const float* wq = (const float*)d_in[1];
    const float* bq = (const float*)d_in[2];
    const float* wk = (const float*)d_in[3];
    const float* bk = (const float*)d_in[4];
    const float* wv = (const float*)d_in[5];
    const float* bv = (const float*)d_in[6];
    const float* wo = (const float*)d_in[7];
    const float* bo = (const float*)d_in[8];
    float* out = (float*)d_out;

    cudaFuncSetAttribute(gemm_tc<0>, cudaFuncAttributeMaxDynamicSharedMemorySize, GEMM_SMEM);
    cudaFuncSetAttribute(gemm_tc<1>, cudaFuncAttributeMaxDynamicSharedMemorySize, GEMM_SMEM);

    transpose_w<<<dim3(32, 32, 4), dim3(32, 8)>>>(wq, wk, wv, wo);
    pack_bias<<<12, 256>>>(bq, bk, bv);
    round_x<<<32768, 256>>>(x);

    // QKV: N_total = 3072 -> 24 n-tiles, n-fastest so concurrent CTAs share A in L2
    gemm_tc<0><<<dim3(24, 256), 256, GEMM_SMEM>>>(nullptr, nullptr);

    reduce_partial<<<dim3(8, 32, 4), 128>>>();
    reduce_final<<<16, 256>>>();
    apply_u<<<32768, 256>>>();

    // out: N_total = 1024 -> 8 n-tiles
    gemm_tc<1><<<dim3(8, 256), 256, GEMM_SMEM>>>(bo, out);
}

// round 7
// speedup vs baseline: 2.8437x; 2.8437x over previous
#include <cuda_runtime.h>
#include <cuda_fp16.h>
#include <cstdint>
#include <math.h>

// ---------------- problem constants ----------------
#define NB   4
#define SEQ  8192
#define DIM  1024
#define MTOT (NB*SEQ)          // 32768 rows

// ---------------- GEMM tiling (fp16 operands) -------
#define BM 128
#define BN 128
#define BKH 64                 // 64 halves per k-tile = 128B data per row
#define NK (DIM/BKH)           // 16 k-tiles
#define ROW_STR 144            // padded row stride in BYTES (conflict-free LDS)
#define A_REGION (BM*ROW_STR)  // 18432 B
#define B_REGION (BN*ROW_STR)  // 18432 B
#define STAGE_BYTES (A_REGION + B_REGION)   // 36864 B
#define GEMM_SMEM (2*STAGE_BYTES)           // 73728 B double buffered

// ---------------- device scratch --------------------
__device__ __half g_Xh [(size_t)MTOT*DIM];   // x, fp16
__device__ __half g_Uh [(size_t)MTOT*DIM];   // U, fp16 (input to out-GEMM)
__device__ __half g_WTh [(size_t)3*DIM*DIM]; // [n,k] transposed wq|wk|wv, fp16
__device__ __half g_WoTh[(size_t)DIM*DIM];   // [n,k] transposed wo, fp16
__device__ float g_Q [(size_t)MTOT*DIM];     // Q (elu+1), fp32
__device__ float g_K [(size_t)MTOT*DIM];
__device__ float g_V [(size_t)MTOT*DIM];
__device__ float g_bqkv[3*DIM];
__device__ float g_pKV[32][NB*DIM];
__device__ float g_pKs[32][NB*DIM];
__device__ float g_KV[NB*DIM];
__device__ float g_Ks[NB*DIM];

// ---------------- PTX helpers ----------------------
__device__ __forceinline__ void cp_async16(void* smem_dst, const void* gsrc) {
    uint32_t s = (uint32_t)__cvta_generic_to_shared(smem_dst);
    asm volatile("cp.async.cg.shared.global [%0], [%1], 16;\n" :: "r"(s), "l"(gsrc));
}
#define CP_COMMIT() asm volatile("cp.async.commit_group;\n")
#define CP_WAIT(n)  asm volatile("cp.async.wait_group %0;\n" :: "n"(n))

__device__ __forceinline__ void mma_f16(float& d0, float& d1, float& d2, float& d3,
                                        uint32_t a0, uint32_t a1, uint32_t a2, uint32_t a3,
                                        uint32_t b0, uint32_t b1) {
    asm volatile(
        "mma.sync.aligned.m16n8k16.row.col.f32.f16.f16.f32 "
        "{%0,%1,%2,%3},{%4,%5,%6,%7},{%8,%9},{%0,%1,%2,%3};\n"
        : "+f"(d0), "+f"(d1), "+f"(d2), "+f"(d3)
        : "r"(a0), "r"(a1), "r"(a2), "r"(a3), "r"(b0), "r"(b1));
}

// ---------------- GEMM mainloop helper ---------------------------------------
// A[M,K] row-major fp16 (lda=DIM), BT[N,K] row-major fp16. Round-1 proven
// schedule: double buffer, issue-before-wait, 2 syncs/kt, scalar LDS frags.
__device__ __forceinline__ void gemm_tile_h(const __half* __restrict__ A,
                                            const __half* __restrict__ BT,
                                            int m0, int n0,
                                            char* smem, float acc[4][4][4]) {
    const int tid = threadIdx.x;

    auto issue = [&](int kt, int buf) {
        char* base = smem + buf * STAGE_BYTES;
        const int kb = kt * BKH;
#pragma unroll
        for (int i = 0; i < 4; i++) {              // A: 1024 x 16B chunks
            const int idx = tid + 256 * i;
            const int r = idx >> 3, c = idx & 7;
            cp_async16(base + r * ROW_STR + c * 16,
                       A + (size_t)(m0 + r) * DIM + kb + c * 8);
        }
        char* bbase = base + A_REGION;
#pragma unroll
        for (int i = 0; i < 4; i++) {              // B: 1024 x 16B chunks
            const int idx = tid + 256 * i;
            const int r = idx >> 3, c = idx & 7;
            cp_async16(bbase + r * ROW_STR + c * 16,
                       BT + (size_t)(n0 + r) * DIM + kb + c * 8);
        }
        CP_COMMIT();
    };

    issue(0, 0);

    const int warp = tid >> 5, lane = tid & 31;
    const int wm = warp & 1, wn = warp >> 1;       // 2 (M) x 4 (N) warps, 64x32 tiles
    const int g = lane >> 2, t = lane & 3;

    for (int kt = 0; kt < NK; ++kt) {
        const int buf = kt & 1;
        if (kt + 1 < NK) { issue(kt + 1, buf ^ 1); CP_WAIT(1); }
        else             { CP_WAIT(0); }
        __syncthreads();

        const char* Ab = smem + buf * STAGE_BYTES + (wm * 64 + g) * ROW_STR + t * 4;
        const char* Bb = smem + buf * STAGE_BYTES + A_REGION + (wn * 32 + g) * ROW_STR + t * 4;

#pragma unroll
        for (int ks = 0; ks < 4; ++ks) {           // 4 x (k=16) per 64-half chunk
            uint32_t af[4][4], bf[4][2];
#pragma unroll
            for (int mt = 0; mt < 4; mt++) {
                const char* ap = Ab + mt * 16 * ROW_STR + ks * 32;
                af[mt][0] = *(const uint32_t*)(ap);                      // A[g][2t..]
                af[mt][1] = *(const uint32_t*)(ap + 8 * ROW_STR);        // A[g+8][2t..]
                af[mt][2] = *(const uint32_t*)(ap + 16);                 // A[g][8+2t..]
                af[mt][3] = *(const uint32_t*)(ap + 8 * ROW_STR + 16);   // A[g+8][8+2t..]
            }
#pragma unroll
            for (int nt = 0; nt < 4; nt++) {
                const char* bp = Bb + nt * 8 * ROW_STR + ks * 32;
                bf[nt][0] = *(const uint32_t*)(bp);                      // BT[g][2t..]
                bf[nt][1] = *(const uint32_t*)(bp + 16);                 // BT[g][8+2t..]
            }
#pragma unroll
            for (int mt = 0; mt < 4; mt++)
#pragma unroll
                for (int nt = 0; nt < 4; nt++)
                    mma_f16(acc[mt][nt][0], acc[mt][nt][1], acc[mt][nt][2], acc[mt][nt][3],
                            af[mt][0], af[mt][1], af[mt][2], af[mt][3],
                            bf[nt][0], bf[nt][1]);
        }
        __syncthreads();
    }
}

// ---------------- kernel 1: QKV projection + elu+1 on Q,K -------------------
__global__ void __launch_bounds__(256, 2)
gemm_qkv_h() {
    extern __shared__ char smem[];
    const int n0g = blockIdx.x * BN;               // 0..3071 over concatenated WT
    const int m0  = blockIdx.y * BM;

    float acc[4][4][4] = {};
    gemm_tile_h(g_Xh, g_WTh, m0, n0g, smem, acc);

    const int warp = threadIdx.x >> 5, lane = threadIdx.x & 31;
    const int wm = warp & 1, wn = warp >> 1;
    const int g = lane >> 2, t = lane & 3;

    const int which = n0g >> 10;                   // 0:q 1:k 2:v
    float* outp = (which == 0) ? g_Q : (which == 1) ? g_K : g_V;
    const int n0 = n0g & 1023;
    const bool act = (which < 2);

#pragma unroll
    for (int mt = 0; mt < 4; mt++) {
#pragma unroll
        for (int nt = 0; nt < 4; nt++) {
            const int col  = n0 + wn * 32 + nt * 8 + t * 2;
            const int row0 = m0 + wm * 64 + mt * 16 + g;
            const float b0v = g_bqkv[n0g + wn * 32 + nt * 8 + t * 2];
            const float b1v = g_bqkv[n0g + wn * 32 + nt * 8 + t * 2 + 1];
            float v0 = acc[mt][nt][0] + b0v;
            float v1 = acc[mt][nt][1] + b1v;
            float v2 = acc[mt][nt][2] + b0v;
            float v3 = acc[mt][nt][3] + b1v;
            if (act) {   // elu(x)+1
                v0 = (v0 > 0.f) ? v0 + 1.f : __expf(v0);
                v1 = (v1 > 0.f) ? v1 + 1.f : __expf(v1);
                v2 = (v2 > 0.f) ? v2 + 1.f : __expf(v2);
                v3 = (v3 > 0.f) ? v3 + 1.f : __expf(v3);
            }
            *(float2*)(outp + (size_t)row0 * DIM + col)       = make_float2(v0, v1);
            *(float2*)(outp + (size_t)(row0 + 8) * DIM + col) = make_float2(v2, v3);
        }
    }
}

// ---------------- kernel 4: out = gelu_tanh(U @ wo + bo) --------------------
__global__ void __launch_bounds__(256, 2)
gemm_out_h(const float* __restrict__ bo, float* __restrict__ out) {
    extern __shared__ char smem[];
    const int n0 = blockIdx.x * BN;
    const int m0 = blockIdx.y * BM;

    float acc[4][4][4] = {};
    gemm_tile_h(g_Uh, g_WoTh, m0, n0, smem, acc);

    const int warp = threadIdx.x >> 5, lane = threadIdx.x & 31;
    const int wm = warp & 1, wn = warp >> 1;
    const int g = lane >> 2, t = lane & 3;

#pragma unroll
    for (int mt = 0; mt < 4; mt++) {
#pragma unroll
        for (int nt = 0; nt < 4; nt++) {
            const int col  = n0 + wn * 32 + nt * 8 + t * 2;
            const int row0 = m0 + wm * 64 + mt * 16 + g;
            const float b0v = bo[col], b1v = bo[col + 1];
            float v0 = acc[mt][nt][0] + b0v;
            float v1 = acc[mt][nt][1] + b1v;
            float v2 = acc[mt][nt][2] + b0v;
            float v3 = acc[mt][nt][3] + b1v;
            const float c0 = 0.7978845608028654f, c1 = 0.044715f;
            float u;   // gelu_tanh(v) = v * sigmoid(2u)
            u = c0 * (v0 + c1 * v0 * v0 * v0); v0 = v0 / (1.f + __expf(-2.f * u));
            u = c0 * (v1 + c1 * v1 * v1 * v1); v1 = v1 / (1.f + __expf(-2.f * u));
            u = c0 * (v2 + c1 * v2 * v2 * v2); v2 = v2 / (1.f + __expf(-2.f * u));
            u = c0 * (v3 + c1 * v3 * v3 * v3); v3 = v3 / (1.f + __expf(-2.f * u));
            *(float2*)(out + (size_t)row0 * DIM + col)       = make_float2(v0, v1);
            *(float2*)(out + (size_t)(row0 + 8) * DIM + col) = make_float2(v2, v3);
        }
    }
}

// ---------------- prep kernels ----------------------------------------------
__global__ void conv_x(const float* __restrict__ x) {
    const size_t i = (size_t)blockIdx.x * 256 + threadIdx.x;   // over 8M float4
    float4 v = ((const float4*)x)[i];
    __half2 h01 = __floats2half2_rn(v.x, v.y);
    __half2 h23 = __floats2half2_rn(v.z, v.w);
    ((__half2*)g_Xh)[i * 2]     = h01;
    ((__half2*)g_Xh)[i * 2 + 1] = h23;
}

__global__ void transpose_w(const float* __restrict__ wq, const float* __restrict__ wk,
                            const float* __restrict__ wv, const float* __restrict__ wo) {
    __shared__ float t[32][33];
    const int mz = blockIdx.z;
    const float* W = (mz == 0) ? wq : (mz == 1) ? wk : (mz == 2) ? wv : wo;
    __half* DT = (mz < 3) ? (g_WTh + (size_t)mz * DIM * DIM) : g_WoTh;
    const int k0 = blockIdx.y * 32, nn0 = blockIdx.x * 32;
#pragma unroll
    for (int i = 0; i < 32; i += 8)
        t[threadIdx.y + i][threadIdx.x] = W[(size_t)(k0 + threadIdx.y + i) * DIM + nn0 + threadIdx.x];
    __syncthreads();
#pragma unroll
    for (int i = 0; i < 32; i += 8)
        DT[(size_t)(nn0 + threadIdx.y + i) * DIM + k0 + threadIdx.x] =
            __float2half_rn(t[threadIdx.x][threadIdx.y + i]);
}

__global__ void pack_bias(const float* __restrict__ bq, const float* __restrict__ bk,
                          const float* __restrict__ bv) {
    const int i = blockIdx.x * 256 + threadIdx.x;   // 0..3071
    g_bqkv[i] = (i < 1024) ? bq[i] : (i < 2048) ? bk[i - 1024] : bv[i - 2048];
}

// ---------------- reductions + normalization --------------------------------
__global__ void reduce_partial() {
    const int h  = blockIdx.x * 128 + threadIdx.x;
    const int sc = blockIdx.y;
    const int n  = blockIdx.z;
    const size_t base = ((size_t)(n * SEQ + sc * 256)) * DIM + h;
    const float* Kp = g_K + base;
    const float* Vp = g_V + base;
    float kv = 0.f, ks = 0.f;
#pragma unroll 8
    for (int i = 0; i < 256; i++) {
        const float k = Kp[(size_t)i * DIM];
        const float v = Vp[(size_t)i * DIM];
        kv = fmaf(k, v, kv);
        ks += k;
    }
    g_pKV[sc][n * DIM + h] = kv;
    g_pKs[sc][n * DIM + h] = ks;
}

__global__ void reduce_final() {
    const int idx = blockIdx.x * blockDim.x + threadIdx.x;
    float kv = 0.f, ks = 0.f;
#pragma unroll
    for (int i = 0; i < 32; i++) { kv += g_pKV[i][idx]; ks += g_pKs[i][idx]; }
    g_KV[idx] = kv;
    g_Ks[idx] = ks;
}

__global__ void apply_u() {   // U = Q*KV / (Q*Ksum + 1e-6) -> fp16 g_Uh
    const size_t i4 = (size_t)blockIdx.x * 256 + threadIdx.x;  // over 8M float4
    const size_t f  = i4 * 4;
    const int n = (int)(f >> 23);
    const int h = (int)(f & 1023);
    const float4 q  = ((const float4*)g_Q)[i4];
    const float4 kv = *(const float4*)(g_KV + n * DIM + h);
    const float4 ks = *(const float4*)(g_Ks + n * DIM + h);
    const float u0 = q.x * kv.x / fmaf(q.x, ks.x, 1e-6f);
    const float u1 = q.y * kv.y / fmaf(q.y, ks.y, 1e-6f);
    const float u2 = q.z * kv.z / fmaf(q.z, ks.z, 1e-6f);
    const float u3 = q.w * kv.w / fmaf(q.w, ks.w, 1e-6f);
    ((__half2*)g_Uh)[i4 * 2]     = __floats2half2_rn(u0, u1);
    ((__half2*)g_Uh)[i4 * 2 + 1] = __floats2half2_rn(u2, u3);
}

// ---------------- launch -----------------------------------------------------
extern "C" void kernel_launch(void* const* d_in, const int* in_sizes, int n_in,
                              void* d_out, int out_size) {
    const float* x  = (const float*)d_in[0];
    const float* wq = (const float*)d_in[1];
    const float* bq = (const float*)d_in[2];
    const float* wk = (const float*)d_in[3];
    const float* bk = (const float*)d_in[4];
    const float* wv = (const float*)d_in[5];
    const float* bv = (const float*)d_in[6];
    const float* wo = (const float*)d_in[7];
    const float* bo = (const float*)d_in[8];
    float* out = (float*)d_out;

    cudaFuncSetAttribute(gemm_qkv_h, cudaFuncAttributeMaxDynamicSharedMemorySize, GEMM_SMEM);
    cudaFuncSetAttribute(gemm_out_h, cudaFuncAttributeMaxDynamicSharedMemorySize, GEMM_SMEM);

    transpose_w<<<dim3(32, 32, 4), dim3(32, 8)>>>(wq, wk, wv, wo);
    pack_bias<<<12, 256>>>(bq, bk, bv);
    conv_x<<<32768, 256>>>(x);

    // QKV: N_total = 3072 -> 24 n-tiles, n-fastest so concurrent CTAs share A in L2
    gemm_qkv_h<<<dim3(24, 256), 256, GEMM_SMEM>>>();

    reduce_partial<<<dim3(8, 32, 4), 128>>>();
    reduce_final<<<16, 256>>>();
    apply_u<<<32768, 256>>>();

    // out: N_total = 1024 -> 8 n-tiles
    gemm_out_h<<<dim3(8, 256), 256, GEMM_SMEM>>>(bo, out);
}

// round 8
// speedup vs baseline: 2.8503x; 1.0023x over previous
#include <cuda_runtime.h>
#include <cuda_fp16.h>
#include <cstdint>
#include <math.h>

// ---------------- problem constants ----------------
#define NB   4
#define SEQ  8192
#define DIM  1024
#define MTOT (NB*SEQ)          // 32768 rows

// ---------------- GEMM tiling (fp16 operands) -------
#define BM 128
#define BN 128
#define BKH 64                 // 64 halves per k-tile = 128B data per row
#define NK (DIM/BKH)           // 16 k-tiles
#define ROW_STR 144            // padded row stride in BYTES (conflict-free LDS/LDSM)
#define A_REGION (BM*ROW_STR)  // 18432 B
#define B_REGION (BN*ROW_STR)  // 18432 B
#define STAGE_BYTES (A_REGION + B_REGION)   // 36864 B
#define STAGES 3
#define GEMM_SMEM (STAGES*STAGE_BYTES)      // 110592 B -> 2 CTAs/SM (221KB)
#define NTHREADS 128           // 4 warps, each 64x64 warp tile

// ---------------- device scratch --------------------
__device__ __half g_Xh [(size_t)MTOT*DIM];   // x, fp16
__device__ __half g_Uh [(size_t)MTOT*DIM];   // U, fp16 (input to out-GEMM)
__device__ __half g_WTh [(size_t)3*DIM*DIM]; // [n,k] transposed wq|wk|wv, fp16
__device__ __half g_WoTh[(size_t)DIM*DIM];   // [n,k] transposed wo, fp16
__device__ float g_Q [(size_t)MTOT*DIM];     // Q (elu+1), fp32
__device__ float g_K [(size_t)MTOT*DIM];
__device__ float g_V [(size_t)MTOT*DIM];
__device__ float g_bqkv[3*DIM];
__device__ float g_pKV[32][NB*DIM];
__device__ float g_pKs[32][NB*DIM];
__device__ float g_KV[NB*DIM];
__device__ float g_Ks[NB*DIM];

// ---------------- PTX helpers ----------------------
__device__ __forceinline__ void cp_async16(void* smem_dst, const void* gsrc) {
    uint32_t s = (uint32_t)__cvta_generic_to_shared(smem_dst);
    asm volatile("cp.async.cg.shared.global [%0], [%1], 16;\n" :: "r"(s), "l"(gsrc));
}
#define CP_COMMIT() asm volatile("cp.async.commit_group;\n")
#define CP_WAIT(n)  asm volatile("cp.async.wait_group %0;\n" :: "n"(n))

__device__ __forceinline__ void ldsm_x4(uint32_t& r0, uint32_t& r1, uint32_t& r2, uint32_t& r3,
                                        const void* smem_addr) {
    uint32_t s = (uint32_t)__cvta_generic_to_shared(smem_addr);
    asm volatile("ldmatrix.sync.aligned.m8n8.x4.shared.b16 {%0,%1,%2,%3}, [%4];"
                 : "=r"(r0), "=r"(r1), "=r"(r2), "=r"(r3) : "r"(s));
}

__device__ __forceinline__ void mma_f16(float& d0, float& d1, float& d2, float& d3,
                                        uint32_t a0, uint32_t a1, uint32_t a2, uint32_t a3,
                                        uint32_t b0, uint32_t b1) {
    asm volatile(
        "mma.sync.aligned.m16n8k16.row.col.f32.f16.f16.f32 "
        "{%0,%1,%2,%3},{%4,%5,%6,%7},{%8,%9},{%0,%1,%2,%3};\n"
        : "+f"(d0), "+f"(d1), "+f"(d2), "+f"(d3)
        : "r"(a0), "r"(a1), "r"(a2), "r"(a3), "r"(b0), "r"(b1));
}

// ---------------- GEMM mainloop ----------------------------------------------
// A[M,K] row-major fp16 (lda=DIM), BT[N,K] row-major fp16.
// 4 warps: 2(M) x 2(N), warp tile 64x64; ldmatrix.x4 frags; 3-stage cp.async,
// one __syncthreads per k-tile.
__device__ __forceinline__ void gemm_tile_h(const __half* __restrict__ A,
                                            const __half* __restrict__ BT,
                                            int m0, int n0,
                                            char* smem, float acc[4][8][4]) {
    const int tid = threadIdx.x;

    auto issue = [&](int kt, int buf) {
        char* base = smem + buf * STAGE_BYTES;
        const int kb = kt * BKH;
#pragma unroll
        for (int i = 0; i < 8; i++) {              // A: 1024 x 16B chunks / 128 thr
            const int idx = tid + NTHREADS * i;
            const int r = idx >> 3, c = idx & 7;
            cp_async16(base + r * ROW_STR + c * 16,
                       A + (size_t)(m0 + r) * DIM + kb + c * 8);
        }
        char* bbase = base + A_REGION;
#pragma unroll
        for (int i = 0; i < 8; i++) {              // B: 1024 x 16B chunks
            const int idx = tid + NTHREADS * i;
            const int r = idx >> 3, c = idx & 7;
            cp_async16(bbase + r * ROW_STR + c * 16,
                       BT + (size_t)(n0 + r) * DIM + kb + c * 8);
        }
        CP_COMMIT();
    };

    // prologue: 2 stages in flight
    issue(0, 0);
    issue(1, 1);

    const int wid = tid >> 5, lane = tid & 31;
    const int wm = wid & 1, wn = wid >> 1;         // 2(M) x 2(N) warps
    const int quad = lane >> 3, lrow = lane & 7;

    // LDSM address templates (byte offsets within a stage)
    // A 16x16 tile (regs a0..a3 = (r0-7,k0-7)(r8-15,k0-7)(r0-7,k8-15)(r8-15,k8-15))
    const int arow = wm * 64 + (quad & 1) * 8 + lrow;
    const int akof = (quad >> 1) * 16;
    // B pair tile (regs = bf[2p][0], bf[2p][1], bf[2p+1][0], bf[2p+1][1])
    const int brow = wn * 64 + (quad >> 1) * 8 + lrow;
    const int bkof = (quad & 1) * 16;

    uint32_t aoff[4], boff[4];
#pragma unroll
    for (int mt = 0; mt < 4; mt++)
        aoff[mt] = (uint32_t)(arow + mt * 16) * ROW_STR + akof;
#pragma unroll
    for (int p = 0; p < 4; p++)
        boff[p] = (uint32_t)A_REGION + (uint32_t)(brow + p * 16) * ROW_STR + bkof;

    for (int kt = 0; kt < NK; ++kt) {
        const int buf = kt % STAGES;
        CP_WAIT(1);                                 // stage kt resident
        __syncthreads();                            // all warps done with stage kt-1's buffer reuse target
        if (kt + 2 < NK) issue(kt + 2, (kt + 2) % STAGES);
        else             CP_COMMIT();               // keep group count uniform

        const char* base = smem + buf * STAGE_BYTES;
#pragma unroll
        for (int ks = 0; ks < 4; ++ks) {            // 4 x (k=16) per 64-half chunk
            uint32_t af[4][4], bf[4][4];
#pragma unroll
            for (int mt = 0; mt < 4; mt++)
                ldsm_x4(af[mt][0], af[mt][1], af[mt][2], af[mt][3],
                        base + aoff[mt] + ks * 32);
#pragma unroll
            for (int p = 0; p < 4; p++)
                ldsm_x4(bf[p][0], bf[p][1], bf[p][2], bf[p][3],
                        base + boff[p] + ks * 32);
#pragma unroll
            for (int mt = 0; mt < 4; mt++)
#pragma unroll
                for (int nt = 0; nt < 8; nt++)
                    mma_f16(acc[mt][nt][0], acc[mt][nt][1], acc[mt][nt][2], acc[mt][nt][3],
                            af[mt][0], af[mt][1], af[mt][2], af[mt][3],
                            bf[nt >> 1][(nt & 1) * 2], bf[nt >> 1][(nt & 1) * 2 + 1]);
        }
    }
}

// ---------------- kernel 1: QKV projection + elu+1 on Q,K -------------------
__global__ void __launch_bounds__(NTHREADS, 2)
gemm_qkv_h() {
    extern __shared__ char smem[];
    const int n0g = blockIdx.x * BN;               // 0..3071 over concatenated WT
    const int m0  = blockIdx.y * BM;

    float acc[4][8][4] = {};
    gemm_tile_h(g_Xh, g_WTh, m0, n0g, smem, acc);

    const int wid = threadIdx.x >> 5, lane = threadIdx.x & 31;
    const int wm = wid & 1, wn = wid >> 1;
    const int g = lane >> 2, t = lane & 3;

    const int which = n0g >> 10;                   // 0:q 1:k 2:v
    float* outp = (which == 0) ? g_Q : (which == 1) ? g_K : g_V;
    const int n0 = n0g & 1023;
    const bool act = (which < 2);

#pragma unroll
    for (int mt = 0; mt < 4; mt++) {
#pragma unroll
        for (int nt = 0; nt < 8; nt++) {
            const int coff = wn * 64 + nt * 8 + t * 2;
            const int col  = n0 + coff;
            const int row0 = m0 + wm * 64 + mt * 16 + g;
            const float b0v = g_bqkv[n0g + coff];
            const float b1v = g_bqkv[n0g + coff + 1];
            float v0 = acc[mt][nt][0] + b0v;
            float v1 = acc[mt][nt][1] + b1v;
            float v2 = acc[mt][nt][2] + b0v;
            float v3 = acc[mt][nt][3] + b1v;
            if (act) {   // elu(x)+1
                v0 = (v0 > 0.f) ? v0 + 1.f : __expf(v0);
                v1 = (v1 > 0.f) ? v1 + 1.f : __expf(v1);
                v2 = (v2 > 0.f) ? v2 + 1.f : __expf(v2);
                v3 = (v3 > 0.f) ? v3 + 1.f : __expf(v3);
            }
            *(float2*)(outp + (size_t)row0 * DIM + col)       = make_float2(v0, v1);
            *(float2*)(outp + (size_t)(row0 + 8) * DIM + col) = make_float2(v2, v3);
        }
    }
}

// ---------------- kernel 4: out = gelu_tanh(U @ wo + bo) --------------------
__global__ void __launch_bounds__(NTHREADS, 2)
gemm_out_h(const float* __restrict__ bo, float* __restrict__ out) {
    extern __shared__ char smem[];
    const int n0 = blockIdx.x * BN;
    const int m0 = blockIdx.y * BM;

    float acc[4][8][4] = {};
    gemm_tile_h(g_Uh, g_WoTh, m0, n0, smem, acc);

    const int wid = threadIdx.x >> 5, lane = threadIdx.x & 31;
    const int wm = wid & 1, wn = wid >> 1;
    const int g = lane >> 2, t = lane & 3;

#pragma unroll
    for (int mt = 0; mt < 4; mt++) {
#pragma unroll
        for (int nt = 0; nt < 8; nt++) {
            const int col  = n0 + wn * 64 + nt * 8 + t * 2;
            const int row0 = m0 + wm * 64 + mt * 16 + g;
            const float b0v = bo[col], b1v = bo[col + 1];
            float v0 = acc[mt][nt][0] + b0v;
            float v1 = acc[mt][nt][1] + b1v;
            float v2 = acc[mt][nt][2] + b0v;
            float v3 = acc[mt][nt][3] + b1v;
            const float c0 = 0.7978845608028654f, c1 = 0.044715f;
            float u;   // gelu_tanh(v) = v * sigmoid(2u)
            u = c0 * (v0 + c1 * v0 * v0 * v0); v0 = v0 / (1.f + __expf(-2.f * u));
            u = c0 * (v1 + c1 * v1 * v1 * v1); v1 = v1 / (1.f + __expf(-2.f * u));
            u = c0 * (v2 + c1 * v2 * v2 * v2); v2 = v2 / (1.f + __expf(-2.f * u));
            u = c0 * (v3 + c1 * v3 * v3 * v3); v3 = v3 / (1.f + __expf(-2.f * u));
            *(float2*)(out + (size_t)row0 * DIM + col)       = make_float2(v0, v1);
            *(float2*)(out + (size_t)(row0 + 8) * DIM + col) = make_float2(v2, v3);
        }
    }
}

// ---------------- prep kernels ----------------------------------------------
__global__ void conv_x(const float* __restrict__ x) {
    const size_t i = (size_t)blockIdx.x * 256 + threadIdx.x;   // over 8M float4
    float4 v = ((const float4*)x)[i];
    ((__half2*)g_Xh)[i * 2]     = __floats2half2_rn(v.x, v.y);
    ((__half2*)g_Xh)[i * 2 + 1] = __floats2half2_rn(v.z, v.w);
}

__global__ void transpose_w(const float* __restrict__ wq, const float* __restrict__ wk,
                            const float* __restrict__ wv, const float* __restrict__ wo) {
    __shared__ float t[32][33];
    const int mz = blockIdx.z;
    const float* W = (mz == 0) ? wq : (mz == 1) ? wk : (mz == 2) ? wv : wo;
    __half* DT = (mz < 3) ? (g_WTh + (size_t)mz * DIM * DIM) : g_WoTh;
    const int k0 = blockIdx.y * 32, nn0 = blockIdx.x * 32;
#pragma unroll
    for (int i = 0; i < 32; i += 8)
        t[threadIdx.y + i][threadIdx.x] = W[(size_t)(k0 + threadIdx.y + i) * DIM + nn0 + threadIdx.x];
    __syncthreads();
#pragma unroll
    for (int i = 0; i < 32; i += 8)
        DT[(size_t)(nn0 + threadIdx.y + i) * DIM + k0 + threadIdx.x] =
            __float2half_rn(t[threadIdx.x][threadIdx.y + i]);
}

__global__ void pack_bias(const float* __restrict__ bq, const float* __restrict__ bk,
                          const float* __restrict__ bv) {
    const int i = blockIdx.x * 256 + threadIdx.x;   // 0..3071
    g_bqkv[i] = (i < 1024) ? bq[i] : (i < 2048) ? bk[i - 1024] : bv[i - 2048];
}

// ---------------- reductions + normalization --------------------------------
__global__ void reduce_partial() {
    const int h  = blockIdx.x * 128 + threadIdx.x;
    const int sc = blockIdx.y;
    const int n  = blockIdx.z;
    const size_t base = ((size_t)(n * SEQ + sc * 256)) * DIM + h;
    const float* Kp = g_K + base;
    const float* Vp = g_V + base;
    float kv = 0.f, ks = 0.f;
#pragma unroll 8
    for (int i = 0; i < 256; i++) {
        const float k = Kp[(size_t)i * DIM];
        const float v = Vp[(size_t)i * DIM];
        kv = fmaf(k, v, kv);
        ks += k;
    }
    g_pKV[sc][n * DIM + h] = kv;
    g_pKs[sc][n * DIM + h] = ks;
}

__global__ void reduce_final() {
    const int idx = blockIdx.x * blockDim.x + threadIdx.x;
    float kv = 0.f, ks = 0.f;
#pragma unroll
    for (int i = 0; i < 32; i++) { kv += g_pKV[i][idx]; ks += g_pKs[i][idx]; }
    g_KV[idx] = kv;
    g_Ks[idx] = ks;
}

__global__ void apply_u() {   // U = Q*KV / (Q*Ksum + 1e-6) -> fp16 g_Uh
    const size_t i4 = (size_t)blockIdx.x * 256 + threadIdx.x;  // over 8M float4
    const size_t f  = i4 * 4;
    const int n = (int)(f >> 23);
    const int h = (int)(f & 1023);
    const float4 q  = ((const float4*)g_Q)[i4];
    const float4 kv = *(const float4*)(g_KV + n * DIM + h);
    const float4 ks = *(const float4*)(g_Ks + n * DIM + h);
    const float u0 = q.x * kv.x / fmaf(q.x, ks.x, 1e-6f);
    const float u1 = q.y * kv.y / fmaf(q.y, ks.y, 1e-6f);
    const float u2 = q.z * kv.z / fmaf(q.z, ks.z, 1e-6f);
    const float u3 = q.w * kv.w / fmaf(q.w, ks.w, 1e-6f);
    ((__half2*)g_Uh)[i4 * 2]     = __floats2half2_rn(u0, u1);
    ((__half2*)g_Uh)[i4 * 2 + 1] = __floats2half2_rn(u2, u3);
}

// ---------------- launch -----------------------------------------------------
extern "C" void kernel_launch(void* const* d_in, const int* in_sizes, int n_in,
                              void* d_out, int out_size) {
    const float* x  = (const float*)d_in[0];
    const float* wq = (const float*)d_in[1];
    const float* bq = (const float*)d_in[2];
    const float* wk = (const float*)d_in[3];
    const float* bk = (const float*)d_in[4];
    const float* wv = (const float*)d_in[5];
    const float* bv = (const float*)d_in[6];
    const float* wo = (const float*)d_in[7];
    const float* bo = (const float*)d_in[8];
    float* out = (float*)d_out;

    cudaFuncSetAttribute(gemm_qkv_h, cudaFuncAttributeMaxDynamicSharedMemorySize, GEMM_SMEM);
    cudaFuncSetAttribute(gemm_out_h, cudaFuncAttributeMaxDynamicSharedMemorySize, GEMM_SMEM);

    transpose_w<<<dim3(32, 32, 4), dim3(32, 8)>>>(wq, wk, wv, wo);
    pack_bias<<<12, 256>>>(bq, bk, bv);
    conv_x<<<32768, 256>>>(x);

    // QKV: N_total = 3072 -> 24 n-tiles, n-fastest so concurrent CTAs share A in L2
    gemm_qkv_h<<<dim3(24, 256), NTHREADS, GEMM_SMEM>>>();

    reduce_partial<<<dim3(8, 32, 4), 128>>>();
    reduce_final<<<16, 256>>>();
    apply_u<<<32768, 256>>>();

    // out: N_total = 1024 -> 8 n-tiles
    gemm_out_h<<<dim3(8, 256), NTHREADS, GEMM_SMEM>>>(bo, out);
}

// round 11
// speedup vs baseline: 4.7699x; 1.6735x over previous
#include <cuda_runtime.h>
#include <cuda_fp16.h>
#include <cstdint>
#include <math.h>

// ---------------- problem constants ----------------
#define NB   4
#define SEQ  8192
#define DIM  1024
#define MTOT (NB*SEQ)          // 32768 rows

// ---------------- GEMM tiling (fp16 operands) -------
#define BM 128
#define BN 128
#define BKH 64                 // 64 halves per k-tile = 128B data per row
#define NK (DIM/BKH)           // 16 k-tiles
#define ROW_STR 144            // padded row stride in BYTES (conflict-free LDSM)
#define A_REGION (BM*ROW_STR)  // 18432 B
#define B_REGION (BN*ROW_STR)  // 18432 B
#define STAGE_BYTES (A_REGION + B_REGION)   // 36864 B
#define STAGES 3
#define GEMM_SMEM (STAGES*STAGE_BYTES)      // 110592 B -> 2 CTAs/SM
#define NTHREADS 128           // 4 warps, each 64x64 warp tile

// ---------------- device scratch --------------------
__device__ __half g_Xh [(size_t)MTOT*DIM];   // x, fp16
__device__ __half g_WTh [(size_t)2*DIM*DIM]; // [n,k] transposed wk|wv, fp16
__device__ float g_K [(size_t)MTOT*DIM];     // K = elu+1, fp32
__device__ float g_V [(size_t)MTOT*DIM];     // V raw, fp32
__device__ float g_bkv[2*DIM];               // bk | bv
__device__ float g_pKV[32][NB*DIM];
__device__ float g_pKs[32][NB*DIM];
__device__ float g_Urow[NB*DIM];             // KV/Ksum per (n,h)
__device__ float g_outrow[NB*DIM];           // gelu(Urow@wo + bo)

// ---------------- PTX helpers ----------------------
__device__ __forceinline__ void cp_async16(void* smem_dst, const void* gsrc) {
    uint32_t s = (uint32_t)__cvta_generic_to_shared(smem_dst);
    asm volatile("cp.async.cg.shared.global [%0], [%1], 16;\n" :: "r"(s), "l"(gsrc));
}
#define CP_COMMIT() asm volatile("cp.async.commit_group;\n")
#define CP_WAIT(n)  asm volatile("cp.async.wait_group %0;\n" :: "n"(n))

__device__ __forceinline__ void ldsm_x4(uint32_t& r0, uint32_t& r1, uint32_t& r2, uint32_t& r3,
                                        const void* smem_addr) {
    uint32_t s = (uint32_t)__cvta_generic_to_shared(smem_addr);
    asm volatile("ldmatrix.sync.aligned.m8n8.x4.shared.b16 {%0,%1,%2,%3}, [%4];"
                 : "=r"(r0), "=r"(r1), "=r"(r2), "=r"(r3) : "r"(s));
}

__device__ __forceinline__ void mma_f16(float& d0, float& d1, float& d2, float& d3,
                                        uint32_t a0, uint32_t a1, uint32_t a2, uint32_t a3,
                                        uint32_t b0, uint32_t b1) {
    asm volatile(
        "mma.sync.aligned.m16n8k16.row.col.f32.f16.f16.f32 "
        "{%0,%1,%2,%3},{%4,%5,%6,%7},{%8,%9},{%0,%1,%2,%3};\n"
        : "+f"(d0), "+f"(d1), "+f"(d2), "+f"(d3)
        : "r"(a0), "r"(a1), "r"(a2), "r"(a3), "r"(b0), "r"(b1));
}

// ---------------- GEMM mainloop (proven Round-8 core) ------------------------
// A[M,K] row-major fp16 (lda=DIM), BT[N,K] row-major fp16.
// 4 warps: 2(M) x 2(N), warp tile 64x64; ldmatrix.x4 frags; 3-stage cp.async.
__device__ __forceinline__ void gemm_tile_h(const __half* __restrict__ A,
                                            const __half* __restrict__ BT,
                                            int m0, int n0,
                                            char* smem, float acc[4][8][4]) {
    const int tid = threadIdx.x;

    auto issue = [&](int kt, int buf) {
        char* base = smem + buf * STAGE_BYTES;
        const int kb = kt * BKH;
#pragma unroll
        for (int i = 0; i < 8; i++) {              // A: 1024 x 16B chunks / 128 thr
            const int idx = tid + NTHREADS * i;
            const int r = idx >> 3, c = idx & 7;
            cp_async16(base + r * ROW_STR + c * 16,
                       A + (size_t)(m0 + r) * DIM + kb + c * 8);
        }
        char* bbase = base + A_REGION;
#pragma unroll
        for (int i = 0; i < 8; i++) {              // B: 1024 x 16B chunks
            const int idx = tid + NTHREADS * i;
            const int r = idx >> 3, c = idx & 7;
            cp_async16(bbase + r * ROW_STR + c * 16,
                       BT + (size_t)(n0 + r) * DIM + kb + c * 8);
        }
        CP_COMMIT();
    };

    issue(0, 0);
    issue(1, 1);

    const int wid = tid >> 5, lane = tid & 31;
    const int wm = wid & 1, wn = wid >> 1;         // 2(M) x 2(N) warps
    const int quad = lane >> 3, lrow = lane & 7;

    const int arow = wm * 64 + (quad & 1) * 8 + lrow;
    const int akof = (quad >> 1) * 16;
    const int brow = wn * 64 + (quad >> 1) * 8 + lrow;
    const int bkof = (quad & 1) * 16;

    uint32_t aoff[4], boff[4];
#pragma unroll
    for (int mt = 0; mt < 4; mt++)
        aoff[mt] = (uint32_t)(arow + mt * 16) * ROW_STR + akof;
#pragma unroll
    for (int p = 0; p < 4; p++)
        boff[p] = (uint32_t)A_REGION + (uint32_t)(brow + p * 16) * ROW_STR + bkof;

    for (int kt = 0; kt < NK; ++kt) {
        const int buf = kt % STAGES;
        CP_WAIT(1);
        __syncthreads();
        if (kt + 2 < NK) issue(kt + 2, (kt + 2) % STAGES);
        else             CP_COMMIT();

        const char* base = smem + buf * STAGE_BYTES;
#pragma unroll
        for (int ks = 0; ks < 4; ++ks) {
            uint32_t af[4][4], bf[4][4];
#pragma unroll
            for (int mt = 0; mt < 4; mt++)
                ldsm_x4(af[mt][0], af[mt][1], af[mt][2], af[mt][3],
                        base + aoff[mt] + ks * 32);
#pragma unroll
            for (int p = 0; p < 4; p++)
                ldsm_x4(bf[p][0], bf[p][1], bf[p][2], bf[p][3],
                        base + boff[p] + ks * 32);
#pragma unroll
            for (int mt = 0; mt < 4; mt++)
#pragma unroll
                for (int nt = 0; nt < 8; nt++)
                    mma_f16(acc[mt][nt][0], acc[mt][nt][1], acc[mt][nt][2], acc[mt][nt][3],
                            af[mt][0], af[mt][1], af[mt][2], af[mt][3],
                            bf[nt >> 1][(nt & 1) * 2], bf[nt >> 1][(nt & 1) * 2 + 1]);
        }
    }
}

// ---------------- kernel 1: K,V projections (Q eliminated) ------------------
// grid.x: 16 tiles over concatenated [wk|wv] (2048 cols): 0..7 -> K (elu+1), 8..15 -> V
__global__ void __launch_bounds__(NTHREADS, 2)
gemm_kv_h() {
    extern __shared__ char smem[];
    const int n0g = blockIdx.x * BN;               // 0..2047
    const int m0  = blockIdx.y * BM;

    float acc[4][8][4] = {};
    gemm_tile_h(g_Xh, g_WTh, m0, n0g, smem, acc);

    const int wid = threadIdx.x >> 5, lane = threadIdx.x & 31;
    const int wm = wid & 1, wn = wid >> 1;
    const int g = lane >> 2, t = lane & 3;

    const int which = n0g >> 10;                   // 0:K 1:V
    float* outp = (which == 0) ? g_K : g_V;
    const int n0 = n0g & 1023;

#pragma unroll
    for (int mt = 0; mt < 4; mt++) {
#pragma unroll
        for (int nt = 0; nt < 8; nt++) {
            const int coff = wn * 64 + nt * 8 + t * 2;
            const int col  = n0 + coff;
            const int row0 = m0 + wm * 64 + mt * 16 + g;
            const float b0v = g_bkv[n0g + coff];
            const float b1v = g_bkv[n0g + coff + 1];
            float v0 = acc[mt][nt][0] + b0v;
            float v1 = acc[mt][nt][1] + b1v;
            float v2 = acc[mt][nt][2] + b0v;
            float v3 = acc[mt][nt][3] + b1v;
            if (which == 0) {   // K = elu(x)+1
                v0 = (v0 > 0.f) ? v0 + 1.f : __expf(v0);
                v1 = (v1 > 0.f) ? v1 + 1.f : __expf(v1);
                v2 = (v2 > 0.f) ? v2 + 1.f : __expf(v2);
                v3 = (v3 > 0.f) ? v3 + 1.f : __expf(v3);
            }
            *(float2*)(outp + (size_t)row0 * DIM + col)       = make_float2(v0, v1);
            *(float2*)(outp + (size_t)(row0 + 8) * DIM + col) = make_float2(v2, v3);
        }
    }
}

// ---------------- prep kernels ----------------------------------------------
__global__ void conv_x(const float* __restrict__ x) {
    const size_t i = (size_t)blockIdx.x * 256 + threadIdx.x;   // over 8M float4
    float4 v = ((const float4*)x)[i];
    ((__half2*)g_Xh)[i * 2]     = __floats2half2_rn(v.x, v.y);
    ((__half2*)g_Xh)[i * 2 + 1] = __floats2half2_rn(v.z, v.w);
}

__global__ void transpose_w(const float* __restrict__ wk, const float* __restrict__ wv) {
    __shared__ float t[32][33];
    const int mz = blockIdx.z;                     // 0:wk 1:wv
    const float* W = (mz == 0) ? wk : wv;
    __half* DT = g_WTh + (size_t)mz * DIM * DIM;
    const int k0 = blockIdx.y * 32, nn0 = blockIdx.x * 32;
#pragma unroll
    for (int i = 0; i < 32; i += 8)
        t[threadIdx.y + i][threadIdx.x] = W[(size_t)(k0 + threadIdx.y + i) * DIM + nn0 + threadIdx.x];
    __syncthreads();
#pragma unroll
    for (int i = 0; i < 32; i += 8)
        DT[(size_t)(nn0 + threadIdx.y + i) * DIM + k0 + threadIdx.x] =
            __float2half_rn(t[threadIdx.x][threadIdx.y + i]);
}

__global__ void pack_bias(const float* __restrict__ bk, const float* __restrict__ bv) {
    const int i = blockIdx.x * 256 + threadIdx.x;   // 0..2047
    g_bkv[i] = (i < 1024) ? bk[i] : bv[i - 1024];
}

// ---------------- reductions -------------------------------------------------
__global__ void reduce_partial() {
    const int h  = blockIdx.x * 128 + threadIdx.x;
    const int sc = blockIdx.y;
    const int n  = blockIdx.z;
    const size_t base = ((size_t)(n * SEQ + sc * 256)) * DIM + h;
    const float* Kp = g_K + base;
    const float* Vp = g_V + base;
    float kv = 0.f, ks = 0.f;
#pragma unroll 8
    for (int i = 0; i < 256; i++) {
        const float k = Kp[(size_t)i * DIM];
        const float v = Vp[(size_t)i * DIM];
        kv = fmaf(k, v, kv);
        ks += k;
    }
    g_pKV[sc][n * DIM + h] = kv;
    g_pKs[sc][n * DIM + h] = ks;
}

__global__ void reduce_final_urow() {
    const int idx = blockIdx.x * blockDim.x + threadIdx.x;  // 0..4095 = (n,h)
    float kv = 0.f, ks = 0.f;
#pragma unroll
    for (int i = 0; i < 32; i++) { kv += g_pKV[i][idx]; ks += g_pKs[i][idx]; }
    // U[n,s,h] = KV/(Ksum + 1e-6/Q); the Q-dependent term is <= ~5e-8 relative
    // (Q >= ~3e-3, Ksum ~ 7e3), so the s-independent value is exact to fp32 noise.
    g_Urow[idx] = kv / ks;
}

// ---------------- tiny output: outrow = gelu(Urow @ wo + bo) ----------------
__global__ void gemv_out(const float* __restrict__ wo, const float* __restrict__ bo) {
    __shared__ float U[DIM];
    const int n  = blockIdx.x >> 2;
    const int jb = blockIdx.x & 3;
    const int tid = threadIdx.x;                    // 256 threads
#pragma unroll
    for (int i = 0; i < 4; i++) U[tid * 4 + i] = g_Urow[n * DIM + tid * 4 + i];
    __syncthreads();

    const int j = jb * 256 + tid;
    float acc = bo[j];
#pragma unroll 8
    for (int h = 0; h < DIM; h++)
        acc = fmaf(U[h], wo[(size_t)h * DIM + j], acc);

    const float c0 = 0.7978845608028654f, c1 = 0.044715f;
    const float u = c0 * (acc + c1 * acc * acc * acc);
    g_outrow[n * DIM + j] = acc / (1.f + __expf(-2.f * u));   // gelu_tanh
}

// ---------------- broadcast rows to full output ------------------------------
__global__ void bcast(float* __restrict__ out) {
    const size_t i4 = (size_t)blockIdx.x * 256 + threadIdx.x;  // over 8M float4
    const int n = (int)((i4 * 4) >> 23);
    ((float4*)out)[i4] = ((const float4*)g_outrow)[(n << 8) + (int)(i4 & 255)];
}

// ---------------- launch -----------------------------------------------------
extern "C" void kernel_launch(void* const* d_in, const int* in_sizes, int n_in,
                              void* d_out, int out_size) {
    const float* x  = (const float*)d_in[0];
    const float* wk = (const float*)d_in[3];
    const float* bk = (const float*)d_in[4];
    const float* wv = (const float*)d_in[5];
    const float* bv = (const float*)d_in[6];
    const float* wo = (const float*)d_in[7];
    const float* bo = (const float*)d_in[8];
    float* out = (float*)d_out;

    cudaFuncSetAttribute(gemm_kv_h, cudaFuncAttributeMaxDynamicSharedMemorySize, GEMM_SMEM);

    transpose_w<<<dim3(32, 32, 2), dim3(32, 8)>>>(wk, wv);
    pack_bias<<<8, 256>>>(bk, bv);
    conv_x<<<32768, 256>>>(x);

    // K,V: N_total = 2048 -> 16 n-tiles, n-fastest so concurrent CTAs share x in L2
    gemm_kv_h<<<dim3(16, 256), NTHREADS, GEMM_SMEM>>>();

    reduce_partial<<<dim3(8, 32, 4), 128>>>();
    reduce_final_urow<<<16, 256>>>();
    gemv_out<<<16, 256>>>(wo, bo);
    bcast<<<32768, 256>>>(out);
}

// round 12
// speedup vs baseline: 5.1855x; 1.0871x over previous
#include <cuda_runtime.h>
#include <cuda_fp16.h>
#include <cstdint>
#include <math.h>

// ---------------- problem constants ----------------
#define NB   4
#define SEQ  8192
#define DIM  1024
#define MTOT (NB*SEQ)          // 32768 rows
#define MBLK (MTOT/128)        // 256 row blocks

// ---------------- GEMM tiling (fp16 operands) -------
#define BM 128
#define BN 128                 // 64 K-cols + 64 V-cols (interleaved weight layout)
#define BKH 64                 // 64 halves per k-tile = 128B data per row
#define NK (DIM/BKH)           // 16 k-tiles
#define ROW_STR 144            // padded row stride in BYTES (conflict-free LDSM)
#define A_REGION (BM*ROW_STR)  // 18432 B
#define B_REGION (BN*ROW_STR)  // 18432 B
#define STAGE_BYTES (A_REGION + B_REGION)   // 36864 B
#define STAGES 3
#define GEMM_SMEM (STAGES*STAGE_BYTES)      // 110592 B -> 2 CTAs/SM
#define NTHREADS 128           // 4 warps, each 64x64 warp tile
#define VB_STR 65              // epilogue V-exchange stride (floats)

// ---------------- device scratch --------------------
__device__ __half g_Xh [(size_t)MTOT*DIM];    // x, fp16
__device__ __half g_WTh[(size_t)2*DIM*DIM];   // interleaved: tile j -> [wkT j*64.. | wvT j*64..]
__device__ float g_pKV[MBLK*DIM];             // per-rowblock partial sums (deterministic)
__device__ float g_pKs[MBLK*DIM];
__device__ float g_Urow[NB*DIM];              // KV/Ksum + bv per (n,h)
__device__ float g_outrow[NB*DIM];            // gelu(Urow@wo + bo)

// ---------------- PTX helpers ----------------------
__device__ __forceinline__ void cp_async16(void* smem_dst, const void* gsrc) {
    uint32_t s = (uint32_t)__cvta_generic_to_shared(smem_dst);
    asm volatile("cp.async.cg.shared.global [%0], [%1], 16;\n" :: "r"(s), "l"(gsrc));
}
#define CP_COMMIT() asm volatile("cp.async.commit_group;\n")
#define CP_WAIT(n)  asm volatile("cp.async.wait_group %0;\n" :: "n"(n))

__device__ __forceinline__ void ldsm_x4(uint32_t& r0, uint32_t& r1, uint32_t& r2, uint32_t& r3,
                                        const void* smem_addr) {
    uint32_t s = (uint32_t)__cvta_generic_to_shared(smem_addr);
    asm volatile("ldmatrix.sync.aligned.m8n8.x4.shared.b16 {%0,%1,%2,%3}, [%4];"
                 : "=r"(r0), "=r"(r1), "=r"(r2), "=r"(r3) : "r"(s));
}

__device__ __forceinline__ void mma_f16(float& d0, float& d1, float& d2, float& d3,
                                        uint32_t a0, uint32_t a1, uint32_t a2, uint32_t a3,
                                        uint32_t b0, uint32_t b1) {
    asm volatile(
        "mma.sync.aligned.m16n8k16.row.col.f32.f16.f16.f32 "
        "{%0,%1,%2,%3},{%4,%5,%6,%7},{%8,%9},{%0,%1,%2,%3};\n"
        : "+f"(d0), "+f"(d1), "+f"(d2), "+f"(d3)
        : "r"(a0), "r"(a1), "r"(a2), "r"(a3), "r"(b0), "r"(b1));
}

// ---------------- fused K,V projection + columnwise K*V / K reduction -------
// grid = (16, 256): blockIdx.x = 64-col tile j, blockIdx.y = 128-row block.
// Warps: wid0/1 = K rows[0:64)/[64:128); wid2/3 = V same rows (same cols).
__global__ void __launch_bounds__(NTHREADS, 2)
gemm_kv_fused(const float* __restrict__ bk) {
    extern __shared__ char smem[];
    const int tid = threadIdx.x;
    const int j   = blockIdx.x;                  // col tile (64 cols)
    const int m0  = blockIdx.y * BM;
    const int n0  = j * BN;                      // row offset into interleaved weights

    auto issue = [&](int kt, int buf) {
        char* base = smem + buf * STAGE_BYTES;
        const int kb = kt * BKH;
#pragma unroll
        for (int i = 0; i < 8; i++) {            // A: 1024 x 16B chunks / 128 thr
            const int idx = tid + NTHREADS * i;
            const int r = idx >> 3, c = idx & 7;
            cp_async16(base + r * ROW_STR + c * 16,
                       g_Xh + (size_t)(m0 + r) * DIM + kb + c * 8);
        }
        char* bbase = base + A_REGION;
#pragma unroll
        for (int i = 0; i < 8; i++) {            // B: 1024 x 16B chunks
            const int idx = tid + NTHREADS * i;
            const int r = idx >> 3, c = idx & 7;
            cp_async16(bbase + r * ROW_STR + c * 16,
                       g_WTh + (size_t)(n0 + r) * DIM + kb + c * 8);
        }
        CP_COMMIT();
    };

    issue(0, 0);
    issue(1, 1);

    const int wid = tid >> 5, lane = tid & 31;
    const int wm = wid & 1, wn = wid >> 1;       // wn: 0 = K weights, 1 = V weights
    const int quad = lane >> 3, lrow = lane & 7;

    const int arow = wm * 64 + (quad & 1) * 8 + lrow;
    const int akof = (quad >> 1) * 16;
    const int brow = wn * 64 + (quad >> 1) * 8 + lrow;
    const int bkof = (quad & 1) * 16;

    uint32_t aoff[4], boff[4];
#pragma unroll
    for (int mt = 0; mt < 4; mt++)
        aoff[mt] = (uint32_t)(arow + mt * 16) * ROW_STR + akof;
#pragma unroll
    for (int p = 0; p < 4; p++)
        boff[p] = (uint32_t)A_REGION + (uint32_t)(brow + p * 16) * ROW_STR + bkof;

    float acc[4][8][4] = {};

    for (int kt = 0; kt < NK; ++kt) {
        const int buf = kt % STAGES;
        CP_WAIT(1);
        __syncthreads();
        if (kt + 2 < NK) issue(kt + 2, (kt + 2) % STAGES);
        else             CP_COMMIT();

        const char* base = smem + buf * STAGE_BYTES;
#pragma unroll
        for (int ks = 0; ks < 4; ++ks) {
            uint32_t af[4][4], bf[4][4];
#pragma unroll
            for (int mt = 0; mt < 4; mt++)
                ldsm_x4(af[mt][0], af[mt][1], af[mt][2], af[mt][3],
                        base + aoff[mt] + ks * 32);
#pragma unroll
            for (int p = 0; p < 4; p++)
                ldsm_x4(bf[p][0], bf[p][1], bf[p][2], bf[p][3],
                        base + boff[p] + ks * 32);
#pragma unroll
            for (int mt = 0; mt < 4; mt++)
#pragma unroll
                for (int nt = 0; nt < 8; nt++)
                    mma_f16(acc[mt][nt][0], acc[mt][nt][1], acc[mt][nt][2], acc[mt][nt][3],
                            af[mt][0], af[mt][1], af[mt][2], af[mt][3],
                            bf[nt >> 1][(nt & 1) * 2], bf[nt >> 1][(nt & 1) * 2 + 1]);
        }
    }

    // ---------------- fused epilogue: colsum(K*Vraw), colsum(K) --------------
    const int g = lane >> 2, t = lane & 3;       // mma C layout: row g(+8), col t*2(+1)
    float* Vbuf = (float*)smem;                  // [128][VB_STR] fp32 (stage bufs drained)
    float* kvp  = Vbuf + 128 * VB_STR;           // [2][64]
    float* ksp  = kvp + 2 * 64;                  // [2][64]

    __syncthreads();                             // mainloop smem dead

    if (wn == 1) {                               // V warps: export raw accs
#pragma unroll
        for (int mt = 0; mt < 4; mt++)
#pragma unroll
            for (int nt = 0; nt < 8; nt++) {
                const int r = wm * 64 + mt * 16 + g;
                const int c = nt * 8 + t * 2;
                Vbuf[r * VB_STR + c]           = acc[mt][nt][0];
                Vbuf[r * VB_STR + c + 1]       = acc[mt][nt][1];
                Vbuf[(r + 8) * VB_STR + c]     = acc[mt][nt][2];
                Vbuf[(r + 8) * VB_STR + c + 1] = acc[mt][nt][3];
            }
    }
    __syncthreads();

    if (wn == 0) {                               // K warps: activation + products
        float skv[16], sk[16];
#pragma unroll
        for (int i = 0; i < 16; i++) { skv[i] = 0.f; sk[i] = 0.f; }

#pragma unroll
        for (int nt = 0; nt < 8; nt++) {
            const int c = nt * 8 + t * 2;
            const float b0 = bk[j * 64 + c];
            const float b1 = bk[j * 64 + c + 1];
#pragma unroll
            for (int mt = 0; mt < 4; mt++) {
                const int r = wm * 64 + mt * 16 + g;
                float k0 = acc[mt][nt][0] + b0;
                float k1 = acc[mt][nt][1] + b1;
                float k2 = acc[mt][nt][2] + b0;
                float k3 = acc[mt][nt][3] + b1;
                k0 = (k0 > 0.f) ? k0 + 1.f : __expf(k0);   // elu+1
                k1 = (k1 > 0.f) ? k1 + 1.f : __expf(k1);
                k2 = (k2 > 0.f) ? k2 + 1.f : __expf(k2);
                k3 = (k3 > 0.f) ? k3 + 1.f : __expf(k3);
                const float v0 = Vbuf[r * VB_STR + c];
                const float v1 = Vbuf[r * VB_STR + c + 1];
                const float v2 = Vbuf[(r + 8) * VB_STR + c];
                const float v3 = Vbuf[(r + 8) * VB_STR + c + 1];
                skv[nt * 2]     = fmaf(k0, v0, fmaf(k2, v2, skv[nt * 2]));
                skv[nt * 2 + 1] = fmaf(k1, v1, fmaf(k3, v3, skv[nt * 2 + 1]));
                sk[nt * 2]     += k0 + k2;
                sk[nt * 2 + 1] += k1 + k3;
            }
        }
        // reduce over g (8 row-groups): lane = g*4 + t
#pragma unroll
        for (int i = 0; i < 16; i++) {
            skv[i] += __shfl_down_sync(0xffffffffu, skv[i], 16);
            skv[i] += __shfl_down_sync(0xffffffffu, skv[i], 8);
            skv[i] += __shfl_down_sync(0xffffffffu, skv[i], 4);
            sk[i]  += __shfl_down_sync(0xffffffffu, sk[i], 16);
            sk[i]  += __shfl_down_sync(0xffffffffu, sk[i], 8);
            sk[i]  += __shfl_down_sync(0xffffffffu, sk[i], 4);
        }
        if (lane < 4) {                          // lanes t=0..3 hold the sums
#pragma unroll
            for (int nt = 0; nt < 8; nt++) {
                const int c = nt * 8 + lane * 2;
                kvp[wm * 64 + c]     = skv[nt * 2];
                kvp[wm * 64 + c + 1] = skv[nt * 2 + 1];
                ksp[wm * 64 + c]     = sk[nt * 2];
                ksp[wm * 64 + c + 1] = sk[nt * 2 + 1];
            }
        }
    }
    __syncthreads();

    if (tid < 64) {                              // combine row halves, store partial
        const int colg = j * 64 + tid;
        g_pKV[(size_t)blockIdx.y * DIM + colg] = kvp[tid] + kvp[64 + tid];
        g_pKs[(size_t)blockIdx.y * DIM + colg] = ksp[tid] + ksp[64 + tid];
    }
}

// ---------------- prep kernels ----------------------------------------------
__global__ void conv_x(const float* __restrict__ x) {
    const size_t i = (size_t)blockIdx.x * 256 + threadIdx.x;   // over 8M float4
    float4 v = ((const float4*)x)[i];
    ((__half2*)g_Xh)[i * 2]     = __floats2half2_rn(v.x, v.y);
    ((__half2*)g_Xh)[i * 2 + 1] = __floats2half2_rn(v.z, v.w);
}

// interleaved transpose: col nn of W -> row (nn>>6)*128 + mz*64 + (nn&63)
__global__ void transpose_w(const float* __restrict__ wk, const float* __restrict__ wv) {
    __shared__ float t[32][33];
    const int mz = blockIdx.z;                   // 0:wk 1:wv
    const float* W = (mz == 0) ? wk : wv;
    const int k0 = blockIdx.y * 32, nn0 = blockIdx.x * 32;
#pragma unroll
    for (int i = 0; i < 32; i += 8)
        t[threadIdx.y + i][threadIdx.x] = W[(size_t)(k0 + threadIdx.y + i) * DIM + nn0 + threadIdx.x];
    __syncthreads();
#pragma unroll
    for (int i = 0; i < 32; i += 8) {
        const int nn = nn0 + threadIdx.y + i;
        const int orow = (nn >> 6) * 128 + mz * 64 + (nn & 63);
        g_WTh[(size_t)orow * DIM + k0 + threadIdx.x] =
            __float2half_rn(t[threadIdx.x][threadIdx.y + i]);
    }
}

// ---------------- final reduction + normalization (V-bias folded) -----------
__global__ void reduce_final_urow(const float* __restrict__ bv) {
    const int idx = blockIdx.x * blockDim.x + threadIdx.x;  // 0..4095 = (n,h)
    const int n = idx >> 10, h = idx & 1023;
    float kv = 0.f, ks = 0.f;
#pragma unroll 8
    for (int i = 0; i < 64; i++) {
        kv += g_pKV[(size_t)(n * 64 + i) * DIM + h];
        ks += g_pKs[(size_t)(n * 64 + i) * DIM + h];
    }
    // U[n,s,h] = (KVraw + bv*Ksum)/(Ksum + 1e-6/Q) ~= KVraw/Ksum + bv
    // (Q >= ~3e-3, Ksum ~7e3 -> the 1e-6/Q term is <~5e-8 relative: negligible)
    g_Urow[idx] = kv / ks + bv[h];
}

// ---------------- tiny output: outrow = gelu(Urow @ wo + bo) ----------------
__global__ void gemv_out(const float* __restrict__ wo, const float* __restrict__ bo) {
    __shared__ float U[DIM];
    const int n  = blockIdx.x >> 2;
    const int jb = blockIdx.x & 3;
    const int tid = threadIdx.x;                 // 256 threads
#pragma unroll
    for (int i = 0; i < 4; i++) U[tid * 4 + i] = g_Urow[n * DIM + tid * 4 + i];
    __syncthreads();

    const int jcol = jb * 256 + tid;
    float acc = bo[jcol];
#pragma unroll 8
    for (int h = 0; h < DIM; h++)
        acc = fmaf(U[h], wo[(size_t)h * DIM + jcol], acc);

    const float c0 = 0.7978845608028654f, c1 = 0.044715f;
    const float u = c0 * (acc + c1 * acc * acc * acc);
    g_outrow[n * DIM + jcol] = acc / (1.f + __expf(-2.f * u));   // gelu_tanh
}

// ---------------- broadcast rows to full output ------------------------------
__global__ void bcast(float* __restrict__ out) {
    const size_t i4 = (size_t)blockIdx.x * 256 + threadIdx.x;  // over 8M float4
    const int n = (int)((i4 * 4) >> 23);
    ((float4*)out)[i4] = ((const float4*)g_outrow)[(n << 8) + (int)(i4 & 255)];
}

// ---------------- launch -----------------------------------------------------
extern "C" void kernel_launch(void* const* d_in, const int* in_sizes, int n_in,
                              void* d_out, int out_size) {
    const float* x  = (const float*)d_in[0];
    const float* wk = (const float*)d_in[3];
    const float* bk = (const float*)d_in[4];
    const float* wv = (const float*)d_in[5];
    const float* bv = (const float*)d_in[6];
    const float* wo = (const float*)d_in[7];
    const float* bo = (const float*)d_in[8];
    float* out = (float*)d_out;

    cudaFuncSetAttribute(gemm_kv_fused, cudaFuncAttributeMaxDynamicSharedMemorySize, GEMM_SMEM);

    transpose_w<<<dim3(32, 32, 2), dim3(32, 8)>>>(wk, wv);
    conv_x<<<32768, 256>>>(x);

    // fused K,V GEMM + reduction: grid (col-tile fastest -> x reuse in L2)
    gemm_kv_fused<<<dim3(16, MBLK), NTHREADS, GEMM_SMEM>>>(bk);

    reduce_final_urow<<<16, 256>>>(bv);
    gemv_out<<<16, 256>>>(wo, bo);
    bcast<<<32768, 256>>>(out);
}

// round 13
// speedup vs baseline: 5.7479x; 1.1085x over previous
#include <cuda_runtime.h>
#include <cuda_fp16.h>
#include <cstdint>
#include <math.h>

// ---------------- problem constants ----------------
#define NB   4
#define SEQ  8192
#define DIM  1024
#define MTOT (NB*SEQ)          // 32768 rows
#define MBLK (MTOT/128)        // 256 row blocks

// ---------------- GEMM tiling (fp16 operands) -------
#define BM 128
#define BN 128                 // 64 K-cols + 64 V-cols (interleaved weight layout)
#define BKH 64                 // 64 halves per k-tile = 128B data per row
#define NK (DIM/BKH)           // 16 k-tiles
#define ROW_STR 144            // padded row stride in BYTES (conflict-free LDSM)
#define A_REGION (BM*ROW_STR)  // 18432 B
#define B_REGION (BN*ROW_STR)  // 18432 B
#define STAGE_BYTES (A_REGION + B_REGION)   // 36864 B
#define STAGES 3
#define GEMM_SMEM (STAGES*STAGE_BYTES)      // 110592 B -> 2 CTAs/SM
#define NTHREADS 128           // 4 warps, each 64x64 warp tile
#define VB_STR 65              // epilogue V-exchange stride (floats)

// ---------------- device scratch --------------------
__device__ __half g_Xh [(size_t)MTOT*DIM];    // x, fp16
__device__ __half g_WTh[(size_t)2*DIM*DIM];   // interleaved: tile j -> [wkT j*64.. | wvT j*64..]
__device__ float g_pKV[MBLK*DIM];             // per-rowblock partial sums (deterministic)
__device__ float g_pKs[MBLK*DIM];
__device__ float g_Urow[NB*DIM];              // KV/Ksum + bv per (n,h)
__device__ float g_outrow[NB*DIM];            // gelu(Urow@wo + bo)

// ---------------- PTX helpers ----------------------
__device__ __forceinline__ void cp_async16(void* smem_dst, const void* gsrc) {
    uint32_t s = (uint32_t)__cvta_generic_to_shared(smem_dst);
    asm volatile("cp.async.cg.shared.global [%0], [%1], 16;\n" :: "r"(s), "l"(gsrc));
}
#define CP_COMMIT() asm volatile("cp.async.commit_group;\n")
#define CP_WAIT(n)  asm volatile("cp.async.wait_group %0;\n" :: "n"(n))

__device__ __forceinline__ void ldsm_x4(uint32_t& r0, uint32_t& r1, uint32_t& r2, uint32_t& r3,
                                        const void* smem_addr) {
    uint32_t s = (uint32_t)__cvta_generic_to_shared(smem_addr);
    asm volatile("ldmatrix.sync.aligned.m8n8.x4.shared.b16 {%0,%1,%2,%3}, [%4];"
                 : "=r"(r0), "=r"(r1), "=r"(r2), "=r"(r3) : "r"(s));
}

__device__ __forceinline__ void mma_f16(float& d0, float& d1, float& d2, float& d3,
                                        uint32_t a0, uint32_t a1, uint32_t a2, uint32_t a3,
                                        uint32_t b0, uint32_t b1) {
    asm volatile(
        "mma.sync.aligned.m16n8k16.row.col.f32.f16.f16.f32 "
        "{%0,%1,%2,%3},{%4,%5,%6,%7},{%8,%9},{%0,%1,%2,%3};\n"
        : "+f"(d0), "+f"(d1), "+f"(d2), "+f"(d3)
        : "r"(a0), "r"(a1), "r"(a2), "r"(a3), "r"(b0), "r"(b1));
}

// ---------------- fused K,V projection + columnwise K*V / K reduction -------
// grid = (16, 256): blockIdx.x = 64-col tile j, blockIdx.y = 128-row block.
// Warps: wid0/1 = K rows[0:64)/[64:128); wid2/3 = V same rows (same cols).
__global__ void __launch_bounds__(NTHREADS, 2)
gemm_kv_fused(const float* __restrict__ bk) {
    extern __shared__ char smem[];
    const int tid = threadIdx.x;
    const int j   = blockIdx.x;                  // col tile (64 cols)
    const int m0  = blockIdx.y * BM;
    const int n0  = j * BN;                      // row offset into interleaved weights

    auto issue = [&](int kt, int buf) {
        char* base = smem + buf * STAGE_BYTES;
        const int kb = kt * BKH;
#pragma unroll
        for (int i = 0; i < 8; i++) {            // A: 1024 x 16B chunks / 128 thr
            const int idx = tid + NTHREADS * i;
            const int r = idx >> 3, c = idx & 7;
            cp_async16(base + r * ROW_STR + c * 16,
                       g_Xh + (size_t)(m0 + r) * DIM + kb + c * 8);
        }
        char* bbase = base + A_REGION;
#pragma unroll
        for (int i = 0; i < 8; i++) {            // B: 1024 x 16B chunks
            const int idx = tid + NTHREADS * i;
            const int r = idx >> 3, c = idx & 7;
            cp_async16(bbase + r * ROW_STR + c * 16,
                       g_WTh + (size_t)(n0 + r) * DIM + kb + c * 8);
        }
        CP_COMMIT();
    };

    issue(0, 0);
    issue(1, 1);

    const int wid = tid >> 5, lane = tid & 31;
    const int wm = wid & 1, wn = wid >> 1;       // wn: 0 = K weights, 1 = V weights
    const int quad = lane >> 3, lrow = lane & 7;

    const int arow = wm * 64 + (quad & 1) * 8 + lrow;
    const int akof = (quad >> 1) * 16;
    const int brow = wn * 64 + (quad >> 1) * 8 + lrow;
    const int bkof = (quad & 1) * 16;

    uint32_t aoff[4], boff[4];
#pragma unroll
    for (int mt = 0; mt < 4; mt++)
        aoff[mt] = (uint32_t)(arow + mt * 16) * ROW_STR + akof;
#pragma unroll
    for (int p = 0; p < 4; p++)
        boff[p] = (uint32_t)A_REGION + (uint32_t)(brow + p * 16) * ROW_STR + bkof;

    float acc[4][8][4] = {};

    for (int kt = 0; kt < NK; ++kt) {
        const int buf = kt % STAGES;
        CP_WAIT(1);
        __syncthreads();
        if (kt + 2 < NK) issue(kt + 2, (kt + 2) % STAGES);
        else             CP_COMMIT();

        const char* base = smem + buf * STAGE_BYTES;
#pragma unroll
        for (int ks = 0; ks < 4; ++ks) {
            uint32_t af[4][4], bf[4][4];
#pragma unroll
            for (int mt = 0; mt < 4; mt++)
                ldsm_x4(af[mt][0], af[mt][1], af[mt][2], af[mt][3],
                        base + aoff[mt] + ks * 32);
#pragma unroll
            for (int p = 0; p < 4; p++)
                ldsm_x4(bf[p][0], bf[p][1], bf[p][2], bf[p][3],
                        base + boff[p] + ks * 32);
#pragma unroll
            for (int mt = 0; mt < 4; mt++)
#pragma unroll
                for (int nt = 0; nt < 8; nt++)
                    mma_f16(acc[mt][nt][0], acc[mt][nt][1], acc[mt][nt][2], acc[mt][nt][3],
                            af[mt][0], af[mt][1], af[mt][2], af[mt][3],
                            bf[nt >> 1][(nt & 1) * 2], bf[nt >> 1][(nt & 1) * 2 + 1]);
        }
    }

    // ---------------- fused epilogue: colsum(K*Vraw), colsum(K) --------------
    const int g = lane >> 2, t = lane & 3;       // mma C layout: row g(+8), col t*2(+1)
    float* Vbuf = (float*)smem;                  // [128][VB_STR] fp32 (stage bufs drained)
    float* kvp  = Vbuf + 128 * VB_STR;           // [2][64]
    float* ksp  = kvp + 2 * 64;                  // [2][64]

    __syncthreads();                             // mainloop smem dead

    if (wn == 1) {                               // V warps: export raw accs
#pragma unroll
        for (int mt = 0; mt < 4; mt++)
#pragma unroll
            for (int nt = 0; nt < 8; nt++) {
                const int r = wm * 64 + mt * 16 + g;
                const int c = nt * 8 + t * 2;
                Vbuf[r * VB_STR + c]           = acc[mt][nt][0];
                Vbuf[r * VB_STR + c + 1]       = acc[mt][nt][1];
                Vbuf[(r + 8) * VB_STR + c]     = acc[mt][nt][2];
                Vbuf[(r + 8) * VB_STR + c + 1] = acc[mt][nt][3];
            }
    }
    __syncthreads();

    if (wn == 0) {                               // K warps: activation + products
        float skv[16], sk[16];
#pragma unroll
        for (int i = 0; i < 16; i++) { skv[i] = 0.f; sk[i] = 0.f; }

#pragma unroll
        for (int nt = 0; nt < 8; nt++) {
            const int c = nt * 8 + t * 2;
            const float b0 = bk[j * 64 + c];
            const float b1 = bk[j * 64 + c + 1];
#pragma unroll
            for (int mt = 0; mt < 4; mt++) {
                const int r = wm * 64 + mt * 16 + g;
                float k0 = acc[mt][nt][0] + b0;
                float k1 = acc[mt][nt][1] + b1;
                float k2 = acc[mt][nt][2] + b0;
                float k3 = acc[mt][nt][3] + b1;
                k0 = (k0 > 0.f) ? k0 + 1.f : __expf(k0);   // elu+1
                k1 = (k1 > 0.f) ? k1 + 1.f : __expf(k1);
                k2 = (k2 > 0.f) ? k2 + 1.f : __expf(k2);
                k3 = (k3 > 0.f) ? k3 + 1.f : __expf(k3);
                const float v0 = Vbuf[r * VB_STR + c];
                const float v1 = Vbuf[r * VB_STR + c + 1];
                const float v2 = Vbuf[(r + 8) * VB_STR + c];
                const float v3 = Vbuf[(r + 8) * VB_STR + c + 1];
                skv[nt * 2]     = fmaf(k0, v0, fmaf(k2, v2, skv[nt * 2]));
                skv[nt * 2 + 1] = fmaf(k1, v1, fmaf(k3, v3, skv[nt * 2 + 1]));
                sk[nt * 2]     += k0 + k2;
                sk[nt * 2 + 1] += k1 + k3;
            }
        }
        // reduce over g (8 row-groups): lane = g*4 + t
#pragma unroll
        for (int i = 0; i < 16; i++) {
            skv[i] += __shfl_down_sync(0xffffffffu, skv[i], 16);
            skv[i] += __shfl_down_sync(0xffffffffu, skv[i], 8);
            skv[i] += __shfl_down_sync(0xffffffffu, skv[i], 4);
            sk[i]  += __shfl_down_sync(0xffffffffu, sk[i], 16);
            sk[i]  += __shfl_down_sync(0xffffffffu, sk[i], 8);
            sk[i]  += __shfl_down_sync(0xffffffffu, sk[i], 4);
        }
        if (lane < 4) {                          // lanes t=0..3 hold the sums
#pragma unroll
            for (int nt = 0; nt < 8; nt++) {
                const int c = nt * 8 + lane * 2;
                kvp[wm * 64 + c]     = skv[nt * 2];
                kvp[wm * 64 + c + 1] = skv[nt * 2 + 1];
                ksp[wm * 64 + c]     = sk[nt * 2];
                ksp[wm * 64 + c + 1] = sk[nt * 2 + 1];
            }
        }
    }
    __syncthreads();

    if (tid < 64) {                              // combine row halves, store partial
        const int colg = j * 64 + tid;
        g_pKV[(size_t)blockIdx.y * DIM + colg] = kvp[tid] + kvp[64 + tid];
        g_pKs[(size_t)blockIdx.y * DIM + colg] = ksp[tid] + ksp[64 + tid];
    }
}

// ---------------- prep kernels ----------------------------------------------
__global__ void conv_x(const float* __restrict__ x) {
    const size_t i = (size_t)blockIdx.x * 256 + threadIdx.x;   // over 8M float4
    float4 v = ((const float4*)x)[i];
    ((__half2*)g_Xh)[i * 2]     = __floats2half2_rn(v.x, v.y);
    ((__half2*)g_Xh)[i * 2 + 1] = __floats2half2_rn(v.z, v.w);
}

// interleaved transpose: col nn of W -> row (nn>>6)*128 + mz*64 + (nn&63)
__global__ void transpose_w(const float* __restrict__ wk, const float* __restrict__ wv) {
    __shared__ float t[32][33];
    const int mz = blockIdx.z;                   // 0:wk 1:wv
    const float* W = (mz == 0) ? wk : wv;
    const int k0 = blockIdx.y * 32, nn0 = blockIdx.x * 32;
#pragma unroll
    for (int i = 0; i < 32; i += 8)
        t[threadIdx.y + i][threadIdx.x] = W[(size_t)(k0 + threadIdx.y + i) * DIM + nn0 + threadIdx.x];
    __syncthreads();
#pragma unroll
    for (int i = 0; i < 32; i += 8) {
        const int nn = nn0 + threadIdx.y + i;
        const int orow = (nn >> 6) * 128 + mz * 64 + (nn & 63);
        g_WTh[(size_t)orow * DIM + k0 + threadIdx.x] =
            __float2half_rn(t[threadIdx.x][threadIdx.y + i]);
    }
}

// ---------------- final reduction + normalization (V-bias folded) -----------
// 64 blocks x 256 threads; 4 lanes cooperate per (n,h): lane l sums 16 of the
// 64 row-block partials, then shfl-combine. idx-local pairs sit in lanes 4i..4i+3.
__global__ void reduce_final_urow(const float* __restrict__ bv) {
    const int tid = threadIdx.x;
    const int l   = tid & 3;                     // sub-lane
    const int idx = blockIdx.x * 64 + (tid >> 2);  // 0..4095 = (n,h)
    const int n = idx >> 10, h = idx & 1023;
    float kv = 0.f, ks = 0.f;
#pragma unroll
    for (int i = 0; i < 16; i++) {
        const size_t row = (size_t)(n * 64 + l * 16 + i) * DIM + h;
        kv += g_pKV[row];
        ks += g_pKs[row];
    }
    kv += __shfl_down_sync(0xffffffffu, kv, 2);
    ks += __shfl_down_sync(0xffffffffu, ks, 2);
    kv += __shfl_down_sync(0xffffffffu, kv, 1);
    ks += __shfl_down_sync(0xffffffffu, ks, 1);
    if (l == 0) {
        // U[n,s,h] = (KVraw + bv*Ksum)/(Ksum + 1e-6/Q) ~= KVraw/Ksum + bv
        // (Q >= ~3e-3, Ksum ~7e3 -> the 1e-6/Q term is <~5e-8 relative)
        g_Urow[idx] = kv / ks + bv[h];
    }
}

// ---------------- tiny output: outrow = gelu(Urow @ wo + bo) ----------------
// grid (16 jb, 4 n); 256 threads = 64 j-cols x 4 h-groups of 256; smem-reduce.
__global__ void gemv_out(const float* __restrict__ wo, const float* __restrict__ bo) {
    __shared__ float part[4][64];
    const int jb = blockIdx.x, n = blockIdx.y;
    const int tid = threadIdx.x;
    const int jl = tid & 63, hg = tid >> 6;      // j-lane, h-group
    const int jcol = jb * 64 + jl;

    float acc = 0.f;
    const float* Up = g_Urow + n * DIM + hg * 256;
    const float* Wp = wo + (size_t)(hg * 256) * DIM + jcol;
#pragma unroll 8
    for (int h = 0; h < 256; h++)
        acc = fmaf(Up[h], Wp[(size_t)h * DIM], acc);
    part[hg][jl] = acc;
    __syncthreads();

    if (tid < 64) {
        float v = part[0][tid] + part[1][tid] + part[2][tid] + part[3][tid] + bo[jcol];
        const float c0 = 0.7978845608028654f, c1 = 0.044715f;
        const float u = c0 * (v + c1 * v * v * v);
        g_outrow[n * DIM + jcol] = v / (1.f + __expf(-2.f * u));   // gelu_tanh
    }
}

// ---------------- broadcast rows to full output ------------------------------
__global__ void bcast(float* __restrict__ out) {
    const size_t i4 = (size_t)blockIdx.x * 256 + threadIdx.x;  // over 8M float4
    const int n = (int)((i4 * 4) >> 23);
    ((float4*)out)[i4] = ((const float4*)g_outrow)[(n << 8) + (int)(i4 & 255)];
}

// ---------------- launch -----------------------------------------------------
extern "C" void kernel_launch(void* const* d_in, const int* in_sizes, int n_in,
                              void* d_out, int out_size) {
    const float* x  = (const float*)d_in[0];
    const float* wk = (const float*)d_in[3];
    const float* bk = (const float*)d_in[4];
    const float* wv = (const float*)d_in[5];
    const float* bv = (const float*)d_in[6];
    const float* wo = (const float*)d_in[7];
    const float* bo = (const float*)d_in[8];
    float* out = (float*)d_out;

    cudaFuncSetAttribute(gemm_kv_fused, cudaFuncAttributeMaxDynamicSharedMemorySize, GEMM_SMEM);

    transpose_w<<<dim3(32, 32, 2), dim3(32, 8)>>>(wk, wv);
    conv_x<<<32768, 256>>>(x);

    // fused K,V GEMM + reduction: grid (col-tile fastest -> x reuse in L2)
    gemm_kv_fused<<<dim3(16, MBLK), NTHREADS, GEMM_SMEM>>>(bk);

    reduce_final_urow<<<64, 256>>>(bv);
    gemv_out<<<dim3(16, 4), 256>>>(wo, bo);
    bcast<<<32768, 256>>>(out);
}

// round 14
// speedup vs baseline: 5.7962x; 1.0084x over previous
#include <cuda_runtime.h>
#include <cuda_fp16.h>
#include <cstdint>
#include <math.h>

// ---------------- problem constants ----------------
#define NB   4
#define SEQ  8192
#define DIM  1024
#define MTOT (NB*SEQ)          // 32768 rows
#define MBLK (MTOT/128)        // 256 row blocks

// ---------------- GEMM tiling (fp16 operands) -------
#define BM 128
#define BN 128                 // 64 K-cols + 64 V-cols (interleaved weight layout)
#define BKH 64                 // 64 halves per k-tile = 128B data per row
#define NK (DIM/BKH)           // 16 k-tiles
#define ROW_STR 144            // padded row stride in BYTES (conflict-free LDSM)
#define A_REGION (BM*ROW_STR)  // 18432 B
#define B_REGION (BN*ROW_STR)  // 18432 B
#define STAGE_BYTES (A_REGION + B_REGION)   // 36864 B
#define STAGES 3
#define GEMM_SMEM (STAGES*STAGE_BYTES)      // 110592 B -> 2 CTAs/SM
#define NTHREADS 128           // 4 warps, each 64x64 warp tile
#define VB_STR 65              // epilogue V-exchange stride (floats)

// ---------------- device scratch --------------------
__device__ __half g_Xh [(size_t)MTOT*DIM];    // x, fp16
__device__ __half g_WTh[(size_t)2*DIM*DIM];   // interleaved: tile j -> [wkT j*64.. | wvT j*64..]
__device__ float g_pKV[MBLK*DIM];             // per-rowblock partial sums (deterministic)
__device__ float g_pKs[MBLK*DIM];
__device__ float g_Urow[NB*DIM];              // KV/Ksum + bv per (n,h)
__device__ float g_outrow[NB*DIM];            // gelu(Urow@wo + bo)

// ---------------- PTX helpers ----------------------
__device__ __forceinline__ void cp_async16(void* smem_dst, const void* gsrc) {
    uint32_t s = (uint32_t)__cvta_generic_to_shared(smem_dst);
    asm volatile("cp.async.cg.shared.global [%0], [%1], 16;\n" :: "r"(s), "l"(gsrc));
}
#define CP_COMMIT() asm volatile("cp.async.commit_group;\n")
#define CP_WAIT(n)  asm volatile("cp.async.wait_group %0;\n" :: "n"(n))

__device__ __forceinline__ void ldsm_x4(uint32_t& r0, uint32_t& r1, uint32_t& r2, uint32_t& r3,
                                        const void* smem_addr) {
    uint32_t s = (uint32_t)__cvta_generic_to_shared(smem_addr);
    asm volatile("ldmatrix.sync.aligned.m8n8.x4.shared.b16 {%0,%1,%2,%3}, [%4];"
                 : "=r"(r0), "=r"(r1), "=r"(r2), "=r"(r3) : "r"(s));
}

__device__ __forceinline__ void mma_f16(float& d0, float& d1, float& d2, float& d3,
                                        uint32_t a0, uint32_t a1, uint32_t a2, uint32_t a3,
                                        uint32_t b0, uint32_t b1) {
    asm volatile(
        "mma.sync.aligned.m16n8k16.row.col.f32.f16.f16.f32 "
        "{%0,%1,%2,%3},{%4,%5,%6,%7},{%8,%9},{%0,%1,%2,%3};\n"
        : "+f"(d0), "+f"(d1), "+f"(d2), "+f"(d3)
        : "r"(a0), "r"(a1), "r"(a2), "r"(a3), "r"(b0), "r"(b1));
}

// ---------------- fused K,V projection + columnwise K*V / K reduction -------
// grid = (16, 256): blockIdx.x = 64-col tile j, blockIdx.y = 128-row block.
// Warps: wid0/1 = K rows[0:64)/[64:128); wid2/3 = V same rows (same cols).
__global__ void __launch_bounds__(NTHREADS, 2)
gemm_kv_fused(const float* __restrict__ bk) {
    extern __shared__ char smem[];
    const int tid = threadIdx.x;
    const int j   = blockIdx.x;                  // col tile (64 cols)
    const int m0  = blockIdx.y * BM;
    const int n0  = j * BN;                      // row offset into interleaved weights

    auto issue = [&](int kt, int buf) {
        char* base = smem + buf * STAGE_BYTES;
        const int kb = kt * BKH;
#pragma unroll
        for (int i = 0; i < 8; i++) {            // A: 1024 x 16B chunks / 128 thr
            const int idx = tid + NTHREADS * i;
            const int r = idx >> 3, c = idx & 7;
            cp_async16(base + r * ROW_STR + c * 16,
                       g_Xh + (size_t)(m0 + r) * DIM + kb + c * 8);
        }
        char* bbase = base + A_REGION;
#pragma unroll
        for (int i = 0; i < 8; i++) {            // B: 1024 x 16B chunks
            const int idx = tid + NTHREADS * i;
            const int r = idx >> 3, c = idx & 7;
            cp_async16(bbase + r * ROW_STR + c * 16,
                       g_WTh + (size_t)(n0 + r) * DIM + kb + c * 8);
        }
        CP_COMMIT();
    };

    issue(0, 0);
    issue(1, 1);

    const int wid = tid >> 5, lane = tid & 31;
    const int wm = wid & 1, wn = wid >> 1;       // wn: 0 = K weights, 1 = V weights
    const int quad = lane >> 3, lrow = lane & 7;

    const int arow = wm * 64 + (quad & 1) * 8 + lrow;
    const int akof = (quad >> 1) * 16;
    const int brow = wn * 64 + (quad >> 1) * 8 + lrow;
    const int bkof = (quad & 1) * 16;

    uint32_t aoff[4], boff[4];
#pragma unroll
    for (int mt = 0; mt < 4; mt++)
        aoff[mt] = (uint32_t)(arow + mt * 16) * ROW_STR + akof;
#pragma unroll
    for (int p = 0; p < 4; p++)
        boff[p] = (uint32_t)A_REGION + (uint32_t)(brow + p * 16) * ROW_STR + bkof;

    float acc[4][8][4] = {};

    for (int kt = 0; kt < NK; ++kt) {
        const int buf = kt % STAGES;
        CP_WAIT(1);
        __syncthreads();
        if (kt + 2 < NK) issue(kt + 2, (kt + 2) % STAGES);
        else             CP_COMMIT();

        const char* base = smem + buf * STAGE_BYTES;
#pragma unroll
        for (int ks = 0; ks < 4; ++ks) {
            uint32_t af[4][4], bf[4][4];
#pragma unroll
            for (int mt = 0; mt < 4; mt++)
                ldsm_x4(af[mt][0], af[mt][1], af[mt][2], af[mt][3],
                        base + aoff[mt] + ks * 32);
#pragma unroll
            for (int p = 0; p < 4; p++)
                ldsm_x4(bf[p][0], bf[p][1], bf[p][2], bf[p][3],
                        base + boff[p] + ks * 32);
#pragma unroll
            for (int mt = 0; mt < 4; mt++)
#pragma unroll
                for (int nt = 0; nt < 8; nt++)
                    mma_f16(acc[mt][nt][0], acc[mt][nt][1], acc[mt][nt][2], acc[mt][nt][3],
                            af[mt][0], af[mt][1], af[mt][2], af[mt][3],
                            bf[nt >> 1][(nt & 1) * 2], bf[nt >> 1][(nt & 1) * 2 + 1]);
        }
    }

    // ---------------- fused epilogue: colsum(K*Vraw), colsum(K) --------------
    const int g = lane >> 2, t = lane & 3;       // mma C layout: row g(+8), col t*2(+1)
    float* Vbuf = (float*)smem;                  // [128][VB_STR] fp32 (stage bufs drained)
    float* kvp  = Vbuf + 128 * VB_STR;           // [2][64]
    float* ksp  = kvp + 2 * 64;                  // [2][64]

    __syncthreads();                             // mainloop smem dead

    if (wn == 1) {                               // V warps: export raw accs
#pragma unroll
        for (int mt = 0; mt < 4; mt++)
#pragma unroll
            for (int nt = 0; nt < 8; nt++) {
                const int r = wm * 64 + mt * 16 + g;
                const int c = nt * 8 + t * 2;
                Vbuf[r * VB_STR + c]           = acc[mt][nt][0];
                Vbuf[r * VB_STR + c + 1]       = acc[mt][nt][1];
                Vbuf[(r + 8) * VB_STR + c]     = acc[mt][nt][2];
                Vbuf[(r + 8) * VB_STR + c + 1] = acc[mt][nt][3];
            }
    }
    __syncthreads();

    if (wn == 0) {                               // K warps: activation + products
        float skv[16], sk[16];
#pragma unroll
        for (int i = 0; i < 16; i++) { skv[i] = 0.f; sk[i] = 0.f; }

#pragma unroll
        for (int nt = 0; nt < 8; nt++) {
            const int c = nt * 8 + t * 2;
            const float b0 = bk[j * 64 + c];
            const float b1 = bk[j * 64 + c + 1];
#pragma unroll
            for (int mt = 0; mt < 4; mt++) {
                const int r = wm * 64 + mt * 16 + g;
                float k0 = acc[mt][nt][0] + b0;
                float k1 = acc[mt][nt][1] + b1;
                float k2 = acc[mt][nt][2] + b0;
                float k3 = acc[mt][nt][3] + b1;
                k0 = (k0 > 0.f) ? k0 + 1.f : __expf(k0);   // elu+1
                k1 = (k1 > 0.f) ? k1 + 1.f : __expf(k1);
                k2 = (k2 > 0.f) ? k2 + 1.f : __expf(k2);
                k3 = (k3 > 0.f) ? k3 + 1.f : __expf(k3);
                const float v0 = Vbuf[r * VB_STR + c];
                const float v1 = Vbuf[r * VB_STR + c + 1];
                const float v2 = Vbuf[(r + 8) * VB_STR + c];
                const float v3 = Vbuf[(r + 8) * VB_STR + c + 1];
                skv[nt * 2]     = fmaf(k0, v0, fmaf(k2, v2, skv[nt * 2]));
                skv[nt * 2 + 1] = fmaf(k1, v1, fmaf(k3, v3, skv[nt * 2 + 1]));
                sk[nt * 2]     += k0 + k2;
                sk[nt * 2 + 1] += k1 + k3;
            }
        }
        // reduce over g (8 row-groups): lane = g*4 + t
#pragma unroll
        for (int i = 0; i < 16; i++) {
            skv[i] += __shfl_down_sync(0xffffffffu, skv[i], 16);
            skv[i] += __shfl_down_sync(0xffffffffu, skv[i], 8);
            skv[i] += __shfl_down_sync(0xffffffffu, skv[i], 4);
            sk[i]  += __shfl_down_sync(0xffffffffu, sk[i], 16);
            sk[i]  += __shfl_down_sync(0xffffffffu, sk[i], 8);
            sk[i]  += __shfl_down_sync(0xffffffffu, sk[i], 4);
        }
        if (lane < 4) {                          // lanes t=0..3 hold the sums
#pragma unroll
            for (int nt = 0; nt < 8; nt++) {
                const int c = nt * 8 + lane * 2;
                kvp[wm * 64 + c]     = skv[nt * 2];
                kvp[wm * 64 + c + 1] = skv[nt * 2 + 1];
                ksp[wm * 64 + c]     = sk[nt * 2];
                ksp[wm * 64 + c + 1] = sk[nt * 2 + 1];
            }
        }
    }
    __syncthreads();

    if (tid < 64) {                              // combine row halves, store partial
        const int colg = j * 64 + tid;
        g_pKV[(size_t)blockIdx.y * DIM + colg] = kvp[tid] + kvp[64 + tid];
        g_pKs[(size_t)blockIdx.y * DIM + colg] = ksp[tid] + ksp[64 + tid];
    }
}

// ---------------- merged prep: weight transpose + x conversion --------------
// blocks [0,2048): interleaved transpose of wk|wv; blocks [2048,34816): x fp32->fp16
__global__ void prep(const float* __restrict__ x,
                     const float* __restrict__ wk, const float* __restrict__ wv) {
    const int b = blockIdx.x;
    const int tid = threadIdx.x;                 // 256
    if (b < 2048) {
        __shared__ float t[32][33];
        const int mz = b >> 10;                  // 0:wk 1:wv
        const float* W = (mz == 0) ? wk : wv;
        const int k0 = ((b >> 5) & 31) * 32, nn0 = (b & 31) * 32;
        const int tx = tid & 31, ty = tid >> 5;  // ty 0..7
#pragma unroll
        for (int i = 0; i < 32; i += 8)
            t[ty + i][tx] = W[(size_t)(k0 + ty + i) * DIM + nn0 + tx];
        __syncthreads();
#pragma unroll
        for (int i = 0; i < 32; i += 8) {
            const int nn = nn0 + ty + i;
            const int orow = (nn >> 6) * 128 + mz * 64 + (nn & 63);
            g_WTh[(size_t)orow * DIM + k0 + tx] = __float2half_rn(t[tx][ty + i]);
        }
    } else {
        const size_t i = (size_t)(b - 2048) * 256 + tid;   // over 8M float4
        float4 v = ((const float4*)x)[i];
        ((__half2*)g_Xh)[i * 2]     = __floats2half2_rn(v.x, v.y);
        ((__half2*)g_Xh)[i * 2 + 1] = __floats2half2_rn(v.z, v.w);
    }
}

// ---------------- final reduction + normalization (V-bias folded) -----------
// 128 blocks x 256 threads; 8 lanes per (n,h): lane l sums 8 of 64 partials.
__global__ void reduce_final_urow(const float* __restrict__ bv) {
    const int tid = threadIdx.x;
    const int l   = tid & 7;                     // sub-lane
    const int idx = blockIdx.x * 32 + (tid >> 3);  // 0..4095 = (n,h)
    const int n = idx >> 10, h = idx & 1023;
    float kv = 0.f, ks = 0.f;
#pragma unroll
    for (int i = 0; i < 8; i++) {
        const size_t row = (size_t)(n * 64 + l * 8 + i) * DIM + h;
        kv += g_pKV[row];
        ks += g_pKs[row];
    }
    kv += __shfl_down_sync(0xffffffffu, kv, 4);
    ks += __shfl_down_sync(0xffffffffu, ks, 4);
    kv += __shfl_down_sync(0xffffffffu, kv, 2);
    ks += __shfl_down_sync(0xffffffffu, ks, 2);
    kv += __shfl_down_sync(0xffffffffu, kv, 1);
    ks += __shfl_down_sync(0xffffffffu, ks, 1);
    if (l == 0) {
        // U[n,s,h] = (KVraw + bv*Ksum)/(Ksum + 1e-6/Q) ~= KVraw/Ksum + bv
        // (Q >= ~3e-3, Ksum ~7e3 -> the 1e-6/Q term is <~5e-8 relative)
        g_Urow[idx] = kv / ks + bv[h];
    }
}

// ---------------- tiny output: outrow = gelu(Urow @ wo + bo) ----------------
// grid (16 jb, 4 n); 256 threads = 64 j-cols x 4 h-groups of 256; smem-reduce.
__global__ void gemv_out(const float* __restrict__ wo, const float* __restrict__ bo) {
    __shared__ float part[4][64];
    const int jb = blockIdx.x, n = blockIdx.y;
    const int tid = threadIdx.x;
    const int jl = tid & 63, hg = tid >> 6;      // j-lane, h-group
    const int jcol = jb * 64 + jl;

    float acc = 0.f;
    const float* Up = g_Urow + n * DIM + hg * 256;
    const float* Wp = wo + (size_t)(hg * 256) * DIM + jcol;
#pragma unroll 8
    for (int h = 0; h < 256; h++)
        acc = fmaf(Up[h], Wp[(size_t)h * DIM], acc);
    part[hg][jl] = acc;
    __syncthreads();

    if (tid < 64) {
        float v = part[0][tid] + part[1][tid] + part[2][tid] + part[3][tid] + bo[jcol];
        const float c0 = 0.7978845608028654f, c1 = 0.044715f;
        const float u = c0 * (v + c1 * v * v * v);
        g_outrow[n * DIM + jcol] = v / (1.f + __expf(-2.f * u));   // gelu_tanh
    }
}

// ---------------- broadcast rows to full output ------------------------------
__global__ void bcast(float* __restrict__ out) {
    const size_t i4 = (size_t)blockIdx.x * 256 + threadIdx.x;  // over 8M float4
    const int n = (int)((i4 * 4) >> 23);
    ((float4*)out)[i4] = ((const float4*)g_outrow)[(n << 8) + (int)(i4 & 255)];
}

// ---------------- launch -----------------------------------------------------
extern "C" void kernel_launch(void* const* d_in, const int* in_sizes, int n_in,
                              void* d_out, int out_size) {
    const float* x  = (const float*)d_in[0];
    const float* wk = (const float*)d_in[3];
    const float* bk = (const float*)d_in[4];
    const float* wv = (const float*)d_in[5];
    const float* bv = (const float*)d_in[6];
    const float* wo = (const float*)d_in[7];
    const float* bo = (const float*)d_in[8];
    float* out = (float*)d_out;

    cudaFuncSetAttribute(gemm_kv_fused, cudaFuncAttributeMaxDynamicSharedMemorySize, GEMM_SMEM);

    prep<<<34816, 256>>>(x, wk, wv);

    // fused K,V GEMM + reduction: grid (col-tile fastest -> x reuse in L2)
    gemm_kv_fused<<<dim3(16, MBLK), NTHREADS, GEMM_SMEM>>>(bk);

    reduce_final_urow<<<128, 256>>>(bv);
    gemv_out<<<dim3(16, 4), 256>>>(wo, bo);
    bcast<<<32768, 256>>>(out);
}

// round 16
// speedup vs baseline: 5.9341x; 1.0238x over previous
#include <cuda_runtime.h>
#include <cuda_fp16.h>
#include <cstdint>
#include <math.h>

// ---------------- problem constants ----------------
#define NB   4
#define SEQ  8192
#define DIM  1024
#define MTOT (NB*SEQ)          // 32768 rows
#define MBLK (MTOT/128)        // 256 row blocks

// ---------------- GEMM tiling (fp16 operands) -------
#define BM 128
#define BN 128                 // 64 K-cols + 64 V-cols (interleaved weight layout)
#define BKH 64                 // 64 halves per k-tile = 128B data per row
#define NK (DIM/BKH)           // 16 k-tiles
#define ROW_STR 144            // padded row stride in BYTES (conflict-free LDSM)
#define A_REGION (BM*ROW_STR)  // 18432 B
#define B_REGION (BN*ROW_STR)  // 18432 B
#define STAGE_BYTES (A_REGION + B_REGION)   // 36864 B
#define STAGES 3
#define GEMM_SMEM (STAGES*STAGE_BYTES)      // 110592 B -> 2 CTAs/SM
#define NTHREADS 128           // 4 warps, each 64x64 warp tile
#define VB_STR 65              // epilogue V-exchange stride (floats)

// ---------------- device scratch --------------------
__device__ __half g_Xh [(size_t)MTOT*DIM];    // x, fp16
__device__ __half g_WTh[(size_t)2*DIM*DIM];   // interleaved: tile j -> [wkT j*64.. | wvT j*64..]
__device__ float g_pKV[MBLK*DIM];             // per-rowblock partial sums (deterministic)
__device__ float g_pKs[MBLK*DIM];
__device__ float g_Urow[NB*DIM];              // KV/Ksum + bv per (n,h)
__device__ float g_opart[32*DIM];             // gemv partials: [hb(8)][n(4)][j(1024)]
__device__ float g_outrow[NB*DIM];            // gelu(Urow@wo + bo)

// ---------------- PTX helpers ----------------------
__device__ __forceinline__ void cp_async16(void* smem_dst, const void* gsrc) {
    uint32_t s = (uint32_t)__cvta_generic_to_shared(smem_dst);
    asm volatile("cp.async.cg.shared.global [%0], [%1], 16;\n" :: "r"(s), "l"(gsrc));
}
#define CP_COMMIT() asm volatile("cp.async.commit_group;\n")
#define CP_WAIT(n)  asm volatile("cp.async.wait_group %0;\n" :: "n"(n))

__device__ __forceinline__ void ldsm_x4(uint32_t& r0, uint32_t& r1, uint32_t& r2, uint32_t& r3,
                                        const void* smem_addr) {
    uint32_t s = (uint32_t)__cvta_generic_to_shared(smem_addr);
    asm volatile("ldmatrix.sync.aligned.m8n8.x4.shared.b16 {%0,%1,%2,%3}, [%4];"
                 : "=r"(r0), "=r"(r1), "=r"(r2), "=r"(r3) : "r"(s));
}

__device__ __forceinline__ void mma_f16(float& d0, float& d1, float& d2, float& d3,
                                        uint32_t a0, uint32_t a1, uint32_t a2, uint32_t a3,
                                        uint32_t b0, uint32_t b1) {
    asm volatile(
        "mma.sync.aligned.m16n8k16.row.col.f32.f16.f16.f32 "
        "{%0,%1,%2,%3},{%4,%5,%6,%7},{%8,%9},{%0,%1,%2,%3};\n"
        : "+f"(d0), "+f"(d1), "+f"(d2), "+f"(d3)
        : "r"(a0), "r"(a1), "r"(a2), "r"(a3), "r"(b0), "r"(b1));
}

// ---------------- fused K,V projection + columnwise K*V / K reduction -------
// grid = (16, 256): blockIdx.x = 64-col tile j, blockIdx.y = 128-row block.
// Warps: wid0/1 = K rows[0:64)/[64:128); wid2/3 = V same rows (same cols).
__global__ void __launch_bounds__(NTHREADS, 2)
gemm_kv_fused(const float* __restrict__ bk) {
    extern __shared__ char smem[];
    const int tid = threadIdx.x;
    const int j   = blockIdx.x;                  // col tile (64 cols)
    const int m0  = blockIdx.y * BM;
    const int n0  = j * BN;                      // row offset into interleaved weights

    auto issue = [&](int kt, int buf) {
        char* base = smem + buf * STAGE_BYTES;
        const int kb = kt * BKH;
#pragma unroll
        for (int i = 0; i < 8; i++) {            // A: 1024 x 16B chunks / 128 thr
            const int idx = tid + NTHREADS * i;
            const int r = idx >> 3, c = idx & 7;
            cp_async16(base + r * ROW_STR + c * 16,
                       g_Xh + (size_t)(m0 + r) * DIM + kb + c * 8);
        }
        char* bbase = base + A_REGION;
#pragma unroll
        for (int i = 0; i < 8; i++) {            // B: 1024 x 16B chunks
            const int idx = tid + NTHREADS * i;
            const int r = idx >> 3, c = idx & 7;
            cp_async16(bbase + r * ROW_STR + c * 16,
                       g_WTh + (size_t)(n0 + r) * DIM + kb + c * 8);
        }
        CP_COMMIT();
    };

    issue(0, 0);
    issue(1, 1);

    const int wid = tid >> 5, lane = tid & 31;
    const int wm = wid & 1, wn = wid >> 1;       // wn: 0 = K weights, 1 = V weights
    const int quad = lane >> 3, lrow = lane & 7;

    const int arow = wm * 64 + (quad & 1) * 8 + lrow;
    const int akof = (quad >> 1) * 16;
    const int brow = wn * 64 + (quad >> 1) * 8 + lrow;
    const int bkof = (quad & 1) * 16;

    uint32_t aoff[4], boff[4];
#pragma unroll
    for (int mt = 0; mt < 4; mt++)
        aoff[mt] = (uint32_t)(arow + mt * 16) * ROW_STR + akof;
#pragma unroll
    for (int p = 0; p < 4; p++)
        boff[p] = (uint32_t)A_REGION + (uint32_t)(brow + p * 16) * ROW_STR + bkof;

    float acc[4][8][4] = {};

    for (int kt = 0; kt < NK; ++kt) {
        const int buf = kt % STAGES;
        CP_WAIT(1);
        __syncthreads();
        if (kt + 2 < NK) issue(kt + 2, (kt + 2) % STAGES);
        else             CP_COMMIT();

        const char* base = smem + buf * STAGE_BYTES;
#pragma unroll
        for (int ks = 0; ks < 4; ++ks) {
            uint32_t af[4][4], bf[4][4];
#pragma unroll
            for (int mt = 0; mt < 4; mt++)
                ldsm_x4(af[mt][0], af[mt][1], af[mt][2], af[mt][3],
                        base + aoff[mt] + ks * 32);
#pragma unroll
            for (int p = 0; p < 4; p++)
                ldsm_x4(bf[p][0], bf[p][1], bf[p][2], bf[p][3],
                        base + boff[p] + ks * 32);
#pragma unroll
            for (int mt = 0; mt < 4; mt++)
#pragma unroll
                for (int nt = 0; nt < 8; nt++)
                    mma_f16(acc[mt][nt][0], acc[mt][nt][1], acc[mt][nt][2], acc[mt][nt][3],
                            af[mt][0], af[mt][1], af[mt][2], af[mt][3],
                            bf[nt >> 1][(nt & 1) * 2], bf[nt >> 1][(nt & 1) * 2 + 1]);
        }
    }

    // ---------------- fused epilogue: colsum(K*Vraw), colsum(K) --------------
    const int g = lane >> 2, t = lane & 3;       // mma C layout: row g(+8), col t*2(+1)
    float* Vbuf = (float*)smem;                  // [128][VB_STR] fp32 (stage bufs drained)
    float* kvp  = Vbuf + 128 * VB_STR;           // [2][64]
    float* ksp  = kvp + 2 * 64;                  // [2][64]

    __syncthreads();                             // mainloop smem dead

    if (wn == 1) {                               // V warps: export raw accs
#pragma unroll
        for (int mt = 0; mt < 4; mt++)
#pragma unroll
            for (int nt = 0; nt < 8; nt++) {
                const int r = wm * 64 + mt * 16 + g;
                const int c = nt * 8 + t * 2;
                Vbuf[r * VB_STR + c]           = acc[mt][nt][0];
                Vbuf[r * VB_STR + c + 1]       = acc[mt][nt][1];
                Vbuf[(r + 8) * VB_STR + c]     = acc[mt][nt][2];
                Vbuf[(r + 8) * VB_STR + c + 1] = acc[mt][nt][3];
            }
    }
    __syncthreads();

    if (wn == 0) {                               // K warps: activation + products
        float skv[16], sk[16];
#pragma unroll
        for (int i = 0; i < 16; i++) { skv[i] = 0.f; sk[i] = 0.f; }

#pragma unroll
        for (int nt = 0; nt < 8; nt++) {
            const int c = nt * 8 + t * 2;
            const float b0 = bk[j * 64 + c];
            const float b1 = bk[j * 64 + c + 1];
#pragma unroll
            for (int mt = 0; mt < 4; mt++) {
                const int r = wm * 64 + mt * 16 + g;
                float k0 = acc[mt][nt][0] + b0;
                float k1 = acc[mt][nt][1] + b1;
                float k2 = acc[mt][nt][2] + b0;
                float k3 = acc[mt][nt][3] + b1;
                k0 = (k0 > 0.f) ? k0 + 1.f : __expf(k0);   // elu+1
                k1 = (k1 > 0.f) ? k1 + 1.f : __expf(k1);
                k2 = (k2 > 0.f) ? k2 + 1.f : __expf(k2);
                k3 = (k3 > 0.f) ? k3 + 1.f : __expf(k3);
                const float v0 = Vbuf[r * VB_STR + c];
                const float v1 = Vbuf[r * VB_STR + c + 1];
                const float v2 = Vbuf[(r + 8) * VB_STR + c];
                const float v3 = Vbuf[(r + 8) * VB_STR + c + 1];
                skv[nt * 2]     = fmaf(k0, v0, fmaf(k2, v2, skv[nt * 2]));
                skv[nt * 2 + 1] = fmaf(k1, v1, fmaf(k3, v3, skv[nt * 2 + 1]));
                sk[nt * 2]     += k0 + k2;
                sk[nt * 2 + 1] += k1 + k3;
            }
        }
        // reduce over g (8 row-groups): lane = g*4 + t
#pragma unroll
        for (int i = 0; i < 16; i++) {
            skv[i] += __shfl_down_sync(0xffffffffu, skv[i], 16);
            skv[i] += __shfl_down_sync(0xffffffffu, skv[i], 8);
            skv[i] += __shfl_down_sync(0xffffffffu, skv[i], 4);
            sk[i]  += __shfl_down_sync(0xffffffffu, sk[i], 16);
            sk[i]  += __shfl_down_sync(0xffffffffu, sk[i], 8);
            sk[i]  += __shfl_down_sync(0xffffffffu, sk[i], 4);
        }
        if (lane < 4) {                          // lanes t=0..3 hold the sums
#pragma unroll
            for (int nt = 0; nt < 8; nt++) {
                const int c = nt * 8 + lane * 2;
                kvp[wm * 64 + c]     = skv[nt * 2];
                kvp[wm * 64 + c + 1] = skv[nt * 2 + 1];
                ksp[wm * 64 + c]     = sk[nt * 2];
                ksp[wm * 64 + c + 1] = sk[nt * 2 + 1];
            }
        }
    }
    __syncthreads();

    if (tid < 64) {                              // combine row halves, store partial
        const int colg = j * 64 + tid;
        g_pKV[(size_t)blockIdx.y * DIM + colg] = kvp[tid] + kvp[64 + tid];
        g_pKs[(size_t)blockIdx.y * DIM + colg] = ksp[tid] + ksp[64 + tid];
    }
}

// ---------------- merged prep: weight transpose + x conversion --------------
// blocks [0,2048): interleaved transpose of wk|wv; blocks [2048,34816): x fp32->fp16
__global__ void prep(const float* __restrict__ x,
                     const float* __restrict__ wk, const float* __restrict__ wv) {
    const int b = blockIdx.x;
    const int tid = threadIdx.x;                 // 256
    if (b < 2048) {
        __shared__ float t[32][33];
        const int mz = b >> 10;                  // 0:wk 1:wv
        const float* W = (mz == 0) ? wk : wv;
        const int k0 = ((b >> 5) & 31) * 32, nn0 = (b & 31) * 32;
        const int tx = tid & 31, ty = tid >> 5;  // ty 0..7
#pragma unroll
        for (int i = 0; i < 32; i += 8)
            t[ty + i][tx] = W[(size_t)(k0 + ty + i) * DIM + nn0 + tx];
        __syncthreads();
#pragma unroll
        for (int i = 0; i < 32; i += 8) {
            const int nn = nn0 + ty + i;
            const int orow = (nn >> 6) * 128 + mz * 64 + (nn & 63);
            g_WTh[(size_t)orow * DIM + k0 + tx] = __float2half_rn(t[tx][ty + i]);
        }
    } else {
        const size_t i = (size_t)(b - 2048) * 256 + tid;   // over 8M float4
        float4 v = ((const float4*)x)[i];
        ((__half2*)g_Xh)[i * 2]     = __floats2half2_rn(v.x, v.y);
        ((__half2*)g_Xh)[i * 2 + 1] = __floats2half2_rn(v.z, v.w);
    }
}

// ---------------- final reduction + normalization (V-bias folded) -----------
// 128 blocks x 256 threads; 8 lanes per (n,h): lane l sums 8 of 64 partials.
__global__ void reduce_final_urow(const float* __restrict__ bv) {
    const int tid = threadIdx.x;
    const int l   = tid & 7;                     // sub-lane
    const int idx = blockIdx.x * 32 + (tid >> 3);  // 0..4095 = (n,h)
    const int n = idx >> 10, h = idx & 1023;
    float kv = 0.f, ks = 0.f;
#pragma unroll
    for (int i = 0; i < 8; i++) {
        const size_t row = (size_t)(n * 64 + l * 8 + i) * DIM + h;
        kv += g_pKV[row];
        ks += g_pKs[row];
    }
    kv += __shfl_down_sync(0xffffffffu, kv, 4);
    ks += __shfl_down_sync(0xffffffffu, ks, 4);
    kv += __shfl_down_sync(0xffffffffu, kv, 2);
    ks += __shfl_down_sync(0xffffffffu, ks, 2);
    kv += __shfl_down_sync(0xffffffffu, kv, 1);
    ks += __shfl_down_sync(0xffffffffu, ks, 1);
    if (l == 0) {
        // U[n,s,h] = (KVraw + bv*Ksum)/(Ksum + 1e-6/Q) ~= KVraw/Ksum + bv
        // (Q >= ~3e-3, Ksum ~7e3 -> the 1e-6/Q term is <~5e-8 relative)
        g_Urow[idx] = kv / ks + bv[h];
    }
}

// ---------------- gemv partials: wo read once, all 4 n per thread -----------
// grid 256 = (32 jb) x (8 hb); block 256 = 32 j-lanes x 8 h-subgroups of 16.
__global__ void gemv_part(const float* __restrict__ wo) {
    __shared__ float p[8][4][33];                // [hg][n][jl] (padded)
    const int jb = blockIdx.x & 31, hb = blockIdx.x >> 5;
    const int tid = threadIdx.x;
    const int jl = tid & 31, hg = tid >> 5;
    const int jcol = jb * 32 + jl;
    const int h0 = hb * 128 + hg * 16;

    float a0 = 0.f, a1 = 0.f, a2 = 0.f, a3 = 0.f;
#pragma unroll
    for (int i = 0; i < 16; i++) {
        const int h = h0 + i;
        const float w = wo[(size_t)h * DIM + jcol];   // coalesced 128B per row
        a0 = fmaf(g_Urow[h],           w, a0);
        a1 = fmaf(g_Urow[DIM + h],     w, a1);
        a2 = fmaf(g_Urow[2 * DIM + h], w, a2);
        a3 = fmaf(g_Urow[3 * DIM + h], w, a3);
    }
    p[hg][0][jl] = a0; p[hg][1][jl] = a1; p[hg][2][jl] = a2; p[hg][3][jl] = a3;
    __syncthreads();

    if (tid < 128) {                             // 4 n x 32 j
        const int n = tid >> 5, jj = tid & 31;
        float s = 0.f;
#pragma unroll
        for (int g2 = 0; g2 < 8; g2++) s += p[g2][n][jj];
        g_opart[(size_t)(hb * 4 + n) * DIM + jb * 32 + jj] = s;
    }
}

// ---------------- combine partials + bias + gelu ----------------------------
__global__ void gemv_combine(const float* __restrict__ bo) {
    const int idx = blockIdx.x * 256 + threadIdx.x;  // 0..4095
    const int n = idx >> 10, jcol = idx & 1023;
    float v = bo[jcol];
#pragma unroll
    for (int hb = 0; hb < 8; hb++) v += g_opart[(size_t)(hb * 4 + n) * DIM + jcol];
    const float c0 = 0.7978845608028654f, c1 = 0.044715f;
    const float u = c0 * (v + c1 * v * v * v);
    g_outrow[n * DIM + jcol] = v / (1.f + __expf(-2.f * u));   // gelu_tanh
}

// ---------------- broadcast rows to full output ------------------------------
__global__ void bcast(float* __restrict__ out) {
    const size_t i4 = (size_t)blockIdx.x * 256 + threadIdx.x;  // over 8M float4
    const int n = (int)((i4 * 4) >> 23);
    ((float4*)out)[i4] = ((const float4*)g_outrow)[(n << 8) + (int)(i4 & 255)];
}

// ---------------- launch -----------------------------------------------------
extern "C" void kernel_launch(void* const* d_in, const int* in_sizes, int n_in,
                              void* d_out, int out_size) {
    const float* x  = (const float*)d_in[0];
    const float* wk = (const float*)d_in[3];
    const float* bk = (const float*)d_in[4];
    const float* wv = (const float*)d_in[5];
    const float* bv = (const float*)d_in[6];
    const float* wo = (const float*)d_in[7];
    const float* bo = (const float*)d_in[8];
    float* out = (float*)d_out;

    cudaFuncSetAttribute(gemm_kv_fused, cudaFuncAttributeMaxDynamicSharedMemorySize, GEMM_SMEM);

    prep<<<34816, 256>>>(x, wk, wv);

    // fused K,V GEMM + reduction: grid (col-tile fastest -> x reuse in L2)
    gemm_kv_fused<<<dim3(16, MBLK), NTHREADS, GEMM_SMEM>>>(bk);

    reduce_final_urow<<<128, 256>>>(bv);
    gemv_part<<<256, 256>>>(wo);
    gemv_combine<<<16, 256>>>(bo);
    bcast<<<32768, 256>>>(out);
}